// round 12
// baseline (speedup 1.0000x reference)
#include <cuda_runtime.h>
#include <cuda_fp16.h>
#include <math.h>

#define D_MODEL 768
#define NHEAD 12
#define HEAD_DIM 64
#define BATCH 4
#define SEQ 1024
#define MTOT (BATCH*SEQ)

// scratch (allocation-free requirement -> device globals)
__device__ __half g_xh[MTOT*D_MODEL];
__device__ __half g_wqkvh[3*D_MODEL*D_MODEL];
__device__ __half g_wouth[D_MODEL*D_MODEL];
__device__ __half g_qh[BATCH*NHEAD*SEQ*HEAD_DIM];
__device__ __half g_kh[BATCH*NHEAD*SEQ*HEAD_DIM];
__device__ __half g_vh[BATCH*NHEAD*SEQ*HEAD_DIM];
__device__ __half g_attnh[MTOT*D_MODEL];

// ---------------------------------------------------------------------------
// helpers
// ---------------------------------------------------------------------------
__device__ __forceinline__ void cp16(void* s, const void* g) {
    unsigned sa = (unsigned)__cvta_generic_to_shared(s);
    asm volatile("cp.async.cg.shared.global [%0], [%1], 16;" :: "r"(sa), "l"(g));
}
#define CP_COMMIT() asm volatile("cp.async.commit_group;")
#define CP_WAIT0()  asm volatile("cp.async.wait_group 0;")
#define CP_WAIT1()  asm volatile("cp.async.wait_group 1;")
#define CP_WAIT2()  asm volatile("cp.async.wait_group 2;")

__device__ __forceinline__ float ex2(float x) {
    float r;
    asm("ex2.approx.ftz.f32 %0, %1;" : "=f"(r) : "f"(x));
    return r;
}

// bit-cast __half2 -> u32 (register reinterpret, no instruction)
__device__ __forceinline__ unsigned h2u(__half2 h) {
    __half2_raw hr = *(__half2_raw*)&h;
    unsigned u = (unsigned)hr.x | ((unsigned)hr.y << 16);
    return u;
}

// warp-collective 8x8 b16 matrix loads (4 matrices per call)
__device__ __forceinline__ void ldsm4(unsigned& r0, unsigned& r1, unsigned& r2,
                                      unsigned& r3, unsigned addr) {
    asm volatile("ldmatrix.sync.aligned.m8n8.x4.shared.b16 {%0,%1,%2,%3}, [%4];"
                 : "=r"(r0), "=r"(r1), "=r"(r2), "=r"(r3) : "r"(addr));
}
__device__ __forceinline__ void ldsm4t(unsigned& r0, unsigned& r1, unsigned& r2,
                                       unsigned& r3, unsigned addr) {
    asm volatile("ldmatrix.sync.aligned.m8n8.x4.trans.shared.b16 {%0,%1,%2,%3}, [%4];"
                 : "=r"(r0), "=r"(r1), "=r"(r2), "=r"(r3) : "r"(addr));
}

// mma.m16n8k16 f16 inputs, f32 accum (documented fragment layouts)
__device__ __forceinline__ void mma16(float* d, const unsigned* a, unsigned b0, unsigned b1) {
    asm volatile(
        "mma.sync.aligned.m16n8k16.row.col.f32.f16.f16.f32 "
        "{%0,%1,%2,%3}, {%4,%5,%6,%7}, {%8,%9}, {%0,%1,%2,%3};"
        : "+f"(d[0]), "+f"(d[1]), "+f"(d[2]), "+f"(d[3])
        : "r"(a[0]), "r"(a[1]), "r"(a[2]), "r"(a[3]), "r"(b0), "r"(b1));
}

// ---------------------------------------------------------------------------
// fp32 -> fp16 conversion pre-pass (which: 0=x, 1=qkv_w, 2=out_w)
// ---------------------------------------------------------------------------
__global__ void to_half(const float* __restrict__ src, int which, int n4)
{
    __half* dst = (which == 0) ? g_xh : (which == 1) ? g_wqkvh : g_wouth;
    int i = blockIdx.x * blockDim.x + threadIdx.x;
    if (i < n4) {
        float4 v = ((const float4*)src)[i];
        __half2* d2 = (__half2*)dst;
        d2[i*2]   = __floats2half2_rn(v.x, v.y);
        d2[i*2+1] = __floats2half2_rn(v.z, v.w);
    }
}

// ---------------------------------------------------------------------------
// fp16 GEMM: C[m,n] = sum_k A[m,k]*W[n,k] + bias[n]
// Block 128x128, K-chunk 64, 3-stage cp.async pipeline (ONE sync per iter),
// 256 thr (8 warps), warp tile 32x64, operands via ldmatrix.x4.
// mode 0: A = g_xh,    epilogue -> half, scattered into g_qh/g_kh/g_vh [B,H,T,64]
// mode 1: A = g_attnh, epilogue -> f32 Cout row-major [4096,768]
// ---------------------------------------------------------------------------
#define LDH 72
#define GST (2*128*LDH)   // halves per stage (A tile + B tile)
__global__ __launch_bounds__(256, 2) void gemm_half(
    const float* __restrict__ bias,
    float* __restrict__ Cout,
    int mode)
{
    extern __shared__ __align__(16) char smraw[];
    __half* st = (__half*)smraw;                  // 3 stages x (A 128x72 | B 128x72)
    float*  sBias = (float*)(st + 3*GST);         // 128 floats

    const __half* A = (mode == 0) ? g_xh : g_attnh;
    const __half* W = (mode == 0) ? g_wqkvh : g_wouth;

    const int n0 = blockIdx.x * 128;
    const int m0 = blockIdx.y * 128;
    const int tid = threadIdx.x;
    const int warp = tid >> 5;
    const int lane = tid & 31;
    const int g = lane >> 2;
    const int t = lane & 3;
    const int wm = warp & 3;   // 4 m-slabs of 32
    const int wn = warp >> 2;  // 2 n-slabs of 64

    // ldmatrix lane address components (bytes)
    const int lmat = lane >> 3, lrow = lane & 7;
    const unsigned laneA = ((unsigned)((lmat & 1)*8 + lrow))*(LDH*2) + (unsigned)(lmat >> 1)*16;
    const unsigned laneB = ((unsigned)((lmat >> 1)*8 + lrow))*(LDH*2) + (unsigned)(lmat & 1)*16;

    auto issue = [&](int kt, int s) {
        __half* as = st + s*GST;
        __half* bs = as + 128*LDH;
        #pragma unroll
        for (int u = 0; u < 4; u++) {
            int idx = tid + u*256;               // 1024 x 16B for A
            int r = idx >> 3, c8 = idx & 7;
            cp16(&as[r*LDH + c8*8], &A[(size_t)(m0 + r)*768 + kt + c8*8]);
        }
        #pragma unroll
        for (int u = 0; u < 4; u++) {
            int idx = tid + u*256;
            int r = idx >> 3, c8 = idx & 7;
            cp16(&bs[r*LDH + c8*8], &W[(size_t)(n0 + r)*768 + kt + c8*8]);
        }
        CP_COMMIT();
    };

    issue(0, 0);
    issue(64, 1);
    if (tid < 128) sBias[tid] = bias[n0 + tid];

    const unsigned stBase = (unsigned)__cvta_generic_to_shared(st);

    float c[2][8][4];
    #pragma unroll
    for (int mf = 0; mf < 2; mf++)
        #pragma unroll
        for (int nf = 0; nf < 8; nf++)
            #pragma unroll
            for (int e = 0; e < 4; e++) c[mf][nf][e] = 0.0f;

    for (int it = 0; it < 12; it++) {
        CP_WAIT1();                 // stage it resident
        __syncthreads();            // all warps done with compute(it-1)
        if (it + 2 < 12) issue((it + 2)*64, (it + 2) % 3);   // overwrites buf (it-1)%3: safe
        else CP_COMMIT();

        const unsigned as_s = stBase + (unsigned)((it % 3)*GST*2);
        const unsigned bs_s = as_s + 128*LDH*2;

        #pragma unroll
        for (int kc = 0; kc < 4; kc++) {
            unsigned a[2][4];
            #pragma unroll
            for (int mf = 0; mf < 2; mf++)
                ldsm4(a[mf][0], a[mf][1], a[mf][2], a[mf][3],
                      as_s + laneA + (unsigned)(((wm*32 + mf*16)*LDH + kc*16)*2));
            #pragma unroll
            for (int nfp = 0; nfp < 4; nfp++) {
                unsigned b0a, b1a, b0b, b1b;
                ldsm4(b0a, b1a, b0b, b1b,
                      bs_s + laneB + (unsigned)(((wn*64 + nfp*16)*LDH + kc*16)*2));
                mma16(c[0][2*nfp],   a[0], b0a, b1a);
                mma16(c[1][2*nfp],   a[1], b0a, b1a);
                mma16(c[0][2*nfp+1], a[0], b0b, b1b);
                mma16(c[1][2*nfp+1], a[1], b0b, b1b);
            }
        }
    }

    // epilogue: direct stores, known fragment layout
    #pragma unroll
    for (int mf = 0; mf < 2; mf++) {
        #pragma unroll
        for (int nf = 0; nf < 8; nf++) {
            int m = m0 + wm*32 + mf*16 + g;       // rows m and m+8 (same 1024-block)
            int n = n0 + wn*64 + nf*8 + 2*t;
            float bv0 = sBias[n - n0], bv1 = sBias[n - n0 + 1];
            float v00 = c[mf][nf][0] + bv0, v01 = c[mf][nf][1] + bv1;   // row m
            float v10 = c[mf][nf][2] + bv0, v11 = c[mf][nf][3] + bv1;   // row m+8
            if (mode == 1) {
                *(float2*)&Cout[(size_t)m*768 + n]     = make_float2(v00, v01);
                *(float2*)&Cout[(size_t)(m+8)*768 + n] = make_float2(v10, v11);
            } else {
                int c3 = n / 768;
                int rem = n - c3*768;
                int h = rem >> 6, d = rem & 63;
                __half* dst = (c3 == 0) ? g_qh : (c3 == 1) ? g_kh : g_vh;
                int bb = m >> 10, tt = m & 1023;
                size_t rowbase = ((size_t)(bb*NHEAD + h)*SEQ + tt)*64 + d;
                *(__half2*)&dst[rowbase]        = __floats2half2_rn(v00, v01);
                *(__half2*)&dst[rowbase + 8*64] = __floats2half2_rn(v10, v11);
            }
        }
    }
}

// ---------------------------------------------------------------------------
// Flash attention, fp16 mma + ldmatrix, SOFTWARE-PIPELINED:
//   iter it: softmax(it) then [PV(it) + S(it+1)] MMAs back-to-back.
// 4-stage KV ring (live: it,it+1; pending: it+2; issuing: it+3), ONE barrier
// per iter. grid (8 q-tiles, 48 bh), 256 thr = 8 warps x 16 q-rows.
// relT (transposed rel table) overlays stage 3's K half during the prologue.
// ---------------------------------------------------------------------------
#define LDKH 72
#define KST (2*64*LDKH)   // halves per KV stage (K 64x72 | V 64x72)
#define CSC 0.18033688f   // 0.125 * log2(e)

__global__ __launch_bounds__(256, 2) void attn_flash(const float* __restrict__ rel_emb)
{
    extern __shared__ __align__(16) char saraw[];
    __half* stg = (__half*)saraw;               // 4 KV stages
    __half* sQ  = stg + 4*KST;                  // 128 x 72 halves
    float*  sR  = (float*)(sQ + 128*LDKH);      // 128 x 36 floats
    float*  relT = (float*)(stg + 3*KST);       // overlays stage 3 K half (9216 B)

    const int t0 = blockIdx.x * 128;
    const int bh = blockIdx.y;
    const int tid = threadIdx.x;
    const int w = tid >> 5;            // 0..7
    const int lane = tid & 31;
    const int g = lane >> 2;
    const int t = lane & 3;

    const __half* qb = g_qh + ((size_t)bh*SEQ + t0)*64;
    const __half* kb = g_kh + (size_t)bh*SEQ*64;
    const __half* vb = g_vh + (size_t)bh*SEQ*64;

    // ldmatrix lane address components (bytes)
    const int lmat = lane >> 3, lrow = lane & 7;
    const unsigned laneK = ((unsigned)((lmat >> 1)*8 + lrow))*(LDKH*2) + (unsigned)(lmat & 1)*16;
    const unsigned laneV = ((unsigned)((lmat & 1)*8 + lrow))*(LDKH*2) + (unsigned)(lmat >> 1)*16;
    const unsigned laneQ = ((unsigned)((lmat & 1)*8 + lrow))*(LDKH*2) + (unsigned)(lmat >> 1)*16;

    auto issueKV = [&](int s0, int stage) {
        __half* dK = stg + (stage & 3)*KST;
        __half* dV = dK + 64*LDKH;
        #pragma unroll
        for (int u = 0; u < 2; u++) {
            int idx = tid + u*256;               // 512 x 16B per matrix
            int r = idx >> 3, c8 = idx & 7;
            cp16(&dK[r*LDKH + c8*8], &kb[(size_t)(s0 + r)*64 + c8*8]);
            cp16(&dV[r*LDKH + c8*8], &vb[(size_t)(s0 + r)*64 + c8*8]);
        }
        CP_COMMIT();
    };

    issueKV(0, 0);                                 // G1: KV stage 0
    #pragma unroll
    for (int u = 0; u < 4; u++) {                  // G2: Q (128 rows)
        int idx = tid + u*256;
        int r = idx >> 3, c8 = idx & 7;
        cp16(&sQ[r*LDKH + c8*8], &qb[(size_t)r*64 + c8*8]);
    }
    CP_COMMIT();
    issueKV(64, 1);                                // G3: KV stage 1
    issueKV(128, 2);                               // G4: KV stage 2
    // relT (transposed, conflict-free): direct loads into stage-3 K region
    for (int idx = tid; idx < 33*64; idx += 256) {
        int j = idx >> 6, d = idx & 63;
        relT[d*36 + j] = rel_emb[idx];
    }
    CP_WAIT2();                   // G1 (KV0), G2 (Q) complete
    __syncthreads();

    // rel projections: sR[r][j] = (Q[r] . rel[j]) * scale * log2e
    for (int idx = tid; idx < 128*33; idx += 256) {
        int r = idx / 33, j = idx - r*33;
        const __half* qr = &sQ[r*LDKH];
        float acc = 0.0f;
        #pragma unroll 16
        for (int d = 0; d < 64; d++)
            acc += __half2float(qr[d]) * relT[d*36 + j];
        sR[r*36 + j] = acc * CSC;
    }

    // persistent Q A-fragments (warp w: rows w*16..w*16+15)
    const int r0 = w*16 + g;
    unsigned qa[4][4];
    {
        unsigned q_s = (unsigned)__cvta_generic_to_shared(sQ);
        #pragma unroll
        for (int kc = 0; kc < 4; kc++)
            ldsm4(qa[kc][0], qa[kc][1], qa[kc][2], qa[kc][3],
                  q_s + laneQ + (unsigned)((w*16*LDKH + kc*16)*2));
    }

    const unsigned stBase = (unsigned)__cvta_generic_to_shared(stg);

    // S(0) from stage 0 (resident)
    float s[8][4];
    #pragma unroll
    for (int nfp = 0; nfp < 4; nfp++) {
        s[2*nfp][0] = s[2*nfp][1] = s[2*nfp][2] = s[2*nfp][3] = 0.0f;
        s[2*nfp+1][0] = s[2*nfp+1][1] = s[2*nfp+1][2] = s[2*nfp+1][3] = 0.0f;
        #pragma unroll
        for (int kc = 0; kc < 4; kc++) {
            unsigned b0a, b1a, b0b, b1b;
            ldsm4(b0a, b1a, b0b, b1b,
                  stBase + laneK + (unsigned)((nfp*16*LDKH + kc*16)*2));
            mma16(s[2*nfp],   qa[kc], b0a, b1a);
            mma16(s[2*nfp+1], qa[kc], b0b, b1b);
        }
    }

    float o[8][4];
    #pragma unroll
    for (int i = 0; i < 8; i++)
        #pragma unroll
        for (int j = 0; j < 4; j++) o[i][j] = 0.0f;
    float m0v = -INFINITY, m1v = -INFINITY, l0 = 0.0f, l1 = 0.0f;

    const int rowt0 = t0 + r0, rowt1 = rowt0 + 8;

    for (int it = 0; it < 16; it++) {
        if (it >= 13) CP_WAIT0(); else CP_WAIT1();   // stages <= it+1 resident
        __syncthreads();                             // all warps done with iter it-1
        if (it + 3 < 16) issueKV((it + 3)*64, it + 3);   // overwrites stage it-1: safe
        else CP_COMMIT();
        const int s0 = it * 64;

        // ---- softmax(it) on s -> ph; update m,l; rescale o ----
        const bool uni = (s0 >= t0 + 192) || (s0 + 128 <= t0);
        float bc0 = 0.0f, bc1 = 0.0f;
        if (uni) {
            int jj = (s0 > t0) ? 32 : 0;
            bc0 = sR[r0*36 + jj];
            bc1 = sR[(r0+8)*36 + jj];
        }
        float mn0 = -INFINITY, mn1 = -INFINITY;
        #pragma unroll
        for (int nf = 0; nf < 8; nf++) {
            int cc = s0 + nf*8 + 2*t;
            if (uni) {
                s[nf][0] = s[nf][0]*CSC + bc0;
                s[nf][1] = s[nf][1]*CSC + bc0;
                s[nf][2] = s[nf][2]*CSC + bc1;
                s[nf][3] = s[nf][3]*CSC + bc1;
            } else {
                int d00 = cc - rowt0;     d00 = d00 < -16 ? -16 : (d00 > 16 ? 16 : d00);
                int d01 = cc + 1 - rowt0; d01 = d01 < -16 ? -16 : (d01 > 16 ? 16 : d01);
                int d10 = cc - rowt1;     d10 = d10 < -16 ? -16 : (d10 > 16 ? 16 : d10);
                int d11 = cc + 1 - rowt1; d11 = d11 < -16 ? -16 : (d11 > 16 ? 16 : d11);
                s[nf][0] = s[nf][0]*CSC + sR[r0*36 + d00 + 16];
                s[nf][1] = s[nf][1]*CSC + sR[r0*36 + d01 + 16];
                s[nf][2] = s[nf][2]*CSC + sR[(r0+8)*36 + d10 + 16];
                s[nf][3] = s[nf][3]*CSC + sR[(r0+8)*36 + d11 + 16];
            }
            mn0 = fmaxf(mn0, fmaxf(s[nf][0], s[nf][1]));
            mn1 = fmaxf(mn1, fmaxf(s[nf][2], s[nf][3]));
        }
        mn0 = fmaxf(mn0, __shfl_xor_sync(0xffffffffu, mn0, 1));
        mn0 = fmaxf(mn0, __shfl_xor_sync(0xffffffffu, mn0, 2));
        mn1 = fmaxf(mn1, __shfl_xor_sync(0xffffffffu, mn1, 1));
        mn1 = fmaxf(mn1, __shfl_xor_sync(0xffffffffu, mn1, 2));
        float m0n = fmaxf(m0v, mn0);
        float m1n = fmaxf(m1v, mn1);
        float a0 = ex2(m0v - m0n);
        float a1 = ex2(m1v - m1n);
        m0v = m0n; m1v = m1n;

        float ls0 = 0.0f, ls1 = 0.0f;
        unsigned ph[8][2];
        #pragma unroll
        for (int nf = 0; nf < 8; nf++) {
            float p00 = ex2(s[nf][0] - m0n);
            float p01 = ex2(s[nf][1] - m0n);
            float p10 = ex2(s[nf][2] - m1n);
            float p11 = ex2(s[nf][3] - m1n);
            ls0 += p00 + p01;
            ls1 += p10 + p11;
            ph[nf][0] = h2u(__floats2half2_rn(p00, p01));  // row g
            ph[nf][1] = h2u(__floats2half2_rn(p10, p11));  // row g+8
        }
        ls0 += __shfl_xor_sync(0xffffffffu, ls0, 1);
        ls0 += __shfl_xor_sync(0xffffffffu, ls0, 2);
        ls1 += __shfl_xor_sync(0xffffffffu, ls1, 1);
        ls1 += __shfl_xor_sync(0xffffffffu, ls1, 2);
        l0 = l0*a0 + ls0;
        l1 = l1*a1 + ls1;
        #pragma unroll
        for (int dn = 0; dn < 8; dn++) {
            o[dn][0] *= a0; o[dn][1] *= a0;
            o[dn][2] *= a1; o[dn][3] *= a1;
        }

        // ---- MMA phase: PV(it) from V stage it%4, S(it+1) from K stage (it+1)%4 ----
        const unsigned vxc = stBase + (unsigned)((it & 3)*KST*2) + (unsigned)(64*LDKH*2);
        const unsigned kxn = stBase + (unsigned)(((it + 1) & 3)*KST*2);
        const bool more = (it < 15);
        if (more) {
            #pragma unroll
            for (int nf = 0; nf < 8; nf++) {
                s[nf][0] = 0.0f; s[nf][1] = 0.0f; s[nf][2] = 0.0f; s[nf][3] = 0.0f;
            }
        }
        #pragma unroll
        for (int kc = 0; kc < 4; kc++) {
            unsigned a[4] = { ph[2*kc][0], ph[2*kc][1], ph[2*kc+1][0], ph[2*kc+1][1] };
            #pragma unroll
            for (int dnp = 0; dnp < 4; dnp++) {
                unsigned b0a, b1a, b0b, b1b;
                ldsm4t(b0a, b1a, b0b, b1b,
                       vxc + laneV + (unsigned)((kc*16*LDKH + dnp*16)*2));
                mma16(o[2*dnp],   a, b0a, b1a);
                mma16(o[2*dnp+1], a, b0b, b1b);
            }
            if (more) {
                #pragma unroll
                for (int nfp = 0; nfp < 4; nfp++) {
                    unsigned b0a, b1a, b0b, b1b;
                    ldsm4(b0a, b1a, b0b, b1b,
                          kxn + laneK + (unsigned)((nfp*16*LDKH + kc*16)*2));
                    mma16(s[2*nfp],   qa[kc], b0a, b1a);
                    mma16(s[2*nfp+1], qa[kc], b0b, b1b);
                }
            }
        }
    }

    // epilogue: normalize, write half [B,T,H*64]
    const int bb = bh / NHEAD, h = bh - bb*NHEAD;
    const float inv0 = 1.0f / l0;
    const float inv1 = 1.0f / l1;
    __half* o0 = g_attnh + ((size_t)(bb*SEQ + t0 + r0))*D_MODEL + h*64;
    __half* o1 = o0 + (size_t)8*D_MODEL;
    #pragma unroll
    for (int dn = 0; dn < 8; dn++) {
        *(__half2*)(o0 + dn*8 + 2*t) = __floats2half2_rn(o[dn][0]*inv0, o[dn][1]*inv0);
        *(__half2*)(o1 + dn*8 + 2*t) = __floats2half2_rn(o[dn][2]*inv1, o[dn][3]*inv1);
    }
}

// ---------------------------------------------------------------------------
extern "C" void kernel_launch(void* const* d_in, const int* in_sizes, int n_in,
                              void* d_out, int out_size)
{
    const float* x     = (const float*)d_in[0];
    const float* qkv_w = (const float*)d_in[1];
    const float* qkv_b = (const float*)d_in[2];
    const float* out_w = (const float*)d_in[3];
    const float* out_b = (const float*)d_in[4];
    const float* rel   = (const float*)d_in[5];
    float* out = (float*)d_out;

    (void)in_sizes; (void)n_in; (void)out_size;

    const int gemm_smem = 3*GST*2 + 128*4;                     // 111,104 B
    const int attn_smem = 4*KST*2 + 128*LDKH*2 + 128*36*4;     // 110,592 B
    cudaFuncSetAttribute(gemm_half, cudaFuncAttributeMaxDynamicSharedMemorySize, gemm_smem);
    cudaFuncSetAttribute(attn_flash, cudaFuncAttributeMaxDynamicSharedMemorySize, attn_smem);

    // 0) fp32 -> fp16 conversion pre-pass
    to_half<<<(MTOT*D_MODEL/4 + 255)/256, 256>>>(x, 0, MTOT*D_MODEL/4);
    to_half<<<(3*D_MODEL*D_MODEL/4 + 255)/256, 256>>>(qkv_w, 1, 3*D_MODEL*D_MODEL/4);
    to_half<<<(D_MODEL*D_MODEL/4 + 255)/256, 256>>>(out_w, 2, D_MODEL*D_MODEL/4);
    // 1) QKV projection -> half q/k/v [B,H,T,64]
    gemm_half<<<dim3(18, 32), 256, gemm_smem>>>(qkv_b, nullptr, 0);
    // 2) fused flash attention, software-pipelined
    attn_flash<<<dim3(8, 48), 256, attn_smem>>>(rel);
    // 3) output projection
    gemm_half<<<dim3(6, 32), 256, gemm_smem>>>(out_b, out, 1);
}

// round 13
// speedup vs baseline: 1.0461x; 1.0461x over previous
#include <cuda_runtime.h>
#include <cuda_fp16.h>
#include <math.h>

#define D_MODEL 768
#define NHEAD 12
#define HEAD_DIM 64
#define BATCH 4
#define SEQ 1024
#define MTOT (BATCH*SEQ)

// scratch (allocation-free requirement -> device globals)
__device__ __half g_xh[MTOT*D_MODEL];
__device__ __half g_wqkvh[3*D_MODEL*D_MODEL];
__device__ __half g_wouth[D_MODEL*D_MODEL];
__device__ __half g_qh[BATCH*NHEAD*SEQ*HEAD_DIM];
__device__ __half g_kh[BATCH*NHEAD*SEQ*HEAD_DIM];
__device__ __half g_vh[BATCH*NHEAD*SEQ*HEAD_DIM];
__device__ __half g_attnh[MTOT*D_MODEL];

// ---------------------------------------------------------------------------
// helpers
// ---------------------------------------------------------------------------
__device__ __forceinline__ void cp16(void* s, const void* g) {
    unsigned sa = (unsigned)__cvta_generic_to_shared(s);
    asm volatile("cp.async.cg.shared.global [%0], [%1], 16;" :: "r"(sa), "l"(g));
}
#define CP_COMMIT() asm volatile("cp.async.commit_group;")
#define CP_WAIT1()  asm volatile("cp.async.wait_group 1;")

__device__ __forceinline__ float ex2(float x) {
    float r;
    asm("ex2.approx.ftz.f32 %0, %1;" : "=f"(r) : "f"(x));
    return r;
}

// bit-cast __half2 -> u32 (register reinterpret, no instruction)
__device__ __forceinline__ unsigned h2u(__half2 h) {
    __half2_raw hr = *(__half2_raw*)&h;
    unsigned u = (unsigned)hr.x | ((unsigned)hr.y << 16);
    return u;
}

// warp-collective 8x8 b16 matrix loads (4 matrices per call)
__device__ __forceinline__ void ldsm4(unsigned& r0, unsigned& r1, unsigned& r2,
                                      unsigned& r3, unsigned addr) {
    asm volatile("ldmatrix.sync.aligned.m8n8.x4.shared.b16 {%0,%1,%2,%3}, [%4];"
                 : "=r"(r0), "=r"(r1), "=r"(r2), "=r"(r3) : "r"(addr));
}
__device__ __forceinline__ void ldsm4t(unsigned& r0, unsigned& r1, unsigned& r2,
                                       unsigned& r3, unsigned addr) {
    asm volatile("ldmatrix.sync.aligned.m8n8.x4.trans.shared.b16 {%0,%1,%2,%3}, [%4];"
                 : "=r"(r0), "=r"(r1), "=r"(r2), "=r"(r3) : "r"(addr));
}

// mma.m16n8k16 f16 inputs, f32 accum (documented fragment layouts)
__device__ __forceinline__ void mma16(float* d, const unsigned* a, unsigned b0, unsigned b1) {
    asm volatile(
        "mma.sync.aligned.m16n8k16.row.col.f32.f16.f16.f32 "
        "{%0,%1,%2,%3}, {%4,%5,%6,%7}, {%8,%9}, {%0,%1,%2,%3};"
        : "+f"(d[0]), "+f"(d[1]), "+f"(d[2]), "+f"(d[3])
        : "r"(a[0]), "r"(a[1]), "r"(a[2]), "r"(a[3]), "r"(b0), "r"(b1));
}

// ---------------------------------------------------------------------------
// fp32 -> fp16 conversion pre-pass (which: 0=x, 1=qkv_w, 2=out_w)
// ---------------------------------------------------------------------------
__global__ void to_half(const float* __restrict__ src, int which, int n4)
{
    __half* dst = (which == 0) ? g_xh : (which == 1) ? g_wqkvh : g_wouth;
    int i = blockIdx.x * blockDim.x + threadIdx.x;
    if (i < n4) {
        float4 v = ((const float4*)src)[i];
        __half2* d2 = (__half2*)dst;
        d2[i*2]   = __floats2half2_rn(v.x, v.y);
        d2[i*2+1] = __floats2half2_rn(v.z, v.w);
    }
}

// ---------------------------------------------------------------------------
// fp16 GEMM: C[m,n] = sum_k A[m,k]*W[n,k] + bias[n]
// Block 128x128, K-chunk 64, 3-stage cp.async pipeline (ONE sync per iter),
// 256 thr (8 warps), warp tile 32x64, operands via ldmatrix.x4.
// mode 0: A = g_xh,    epilogue -> half, scattered into g_qh/g_kh/g_vh [B,H,T,64]
// mode 1: A = g_attnh, epilogue -> f32 Cout row-major [4096,768]
// ---------------------------------------------------------------------------
#define LDH 72
#define GST (2*128*LDH)   // halves per stage (A tile + B tile)
__global__ __launch_bounds__(256, 2) void gemm_half(
    const float* __restrict__ bias,
    float* __restrict__ Cout,
    int mode)
{
    extern __shared__ __align__(16) char smraw[];
    __half* st = (__half*)smraw;                  // 3 stages x (A 128x72 | B 128x72)
    float*  sBias = (float*)(st + 3*GST);         // 128 floats

    const __half* A = (mode == 0) ? g_xh : g_attnh;
    const __half* W = (mode == 0) ? g_wqkvh : g_wouth;

    const int n0 = blockIdx.x * 128;
    const int m0 = blockIdx.y * 128;
    const int tid = threadIdx.x;
    const int warp = tid >> 5;
    const int lane = tid & 31;
    const int g = lane >> 2;
    const int t = lane & 3;
    const int wm = warp & 3;   // 4 m-slabs of 32
    const int wn = warp >> 2;  // 2 n-slabs of 64

    // ldmatrix lane address components (bytes)
    const int lmat = lane >> 3, lrow = lane & 7;
    const unsigned laneA = ((unsigned)((lmat & 1)*8 + lrow))*(LDH*2) + (unsigned)(lmat >> 1)*16;
    const unsigned laneB = ((unsigned)((lmat >> 1)*8 + lrow))*(LDH*2) + (unsigned)(lmat & 1)*16;

    auto issue = [&](int kt, int s) {
        __half* as = st + s*GST;
        __half* bs = as + 128*LDH;
        #pragma unroll
        for (int u = 0; u < 4; u++) {
            int idx = tid + u*256;               // 1024 x 16B for A
            int r = idx >> 3, c8 = idx & 7;
            cp16(&as[r*LDH + c8*8], &A[(size_t)(m0 + r)*768 + kt + c8*8]);
        }
        #pragma unroll
        for (int u = 0; u < 4; u++) {
            int idx = tid + u*256;
            int r = idx >> 3, c8 = idx & 7;
            cp16(&bs[r*LDH + c8*8], &W[(size_t)(n0 + r)*768 + kt + c8*8]);
        }
        CP_COMMIT();
    };

    issue(0, 0);
    issue(64, 1);
    if (tid < 128) sBias[tid] = bias[n0 + tid];

    const unsigned stBase = (unsigned)__cvta_generic_to_shared(st);

    float c[2][8][4];
    #pragma unroll
    for (int mf = 0; mf < 2; mf++)
        #pragma unroll
        for (int nf = 0; nf < 8; nf++)
            #pragma unroll
            for (int e = 0; e < 4; e++) c[mf][nf][e] = 0.0f;

    for (int it = 0; it < 12; it++) {
        CP_WAIT1();                 // stage it resident
        __syncthreads();            // all warps done with compute(it-1)
        if (it + 2 < 12) issue((it + 2)*64, (it + 2) % 3);   // overwrites buf (it-1)%3: safe
        else CP_COMMIT();

        const unsigned as_s = stBase + (unsigned)((it % 3)*GST*2);
        const unsigned bs_s = as_s + 128*LDH*2;

        #pragma unroll
        for (int kc = 0; kc < 4; kc++) {
            unsigned a[2][4];
            #pragma unroll
            for (int mf = 0; mf < 2; mf++)
                ldsm4(a[mf][0], a[mf][1], a[mf][2], a[mf][3],
                      as_s + laneA + (unsigned)(((wm*32 + mf*16)*LDH + kc*16)*2));
            #pragma unroll
            for (int nfp = 0; nfp < 4; nfp++) {
                unsigned b0a, b1a, b0b, b1b;
                ldsm4(b0a, b1a, b0b, b1b,
                      bs_s + laneB + (unsigned)(((wn*64 + nfp*16)*LDH + kc*16)*2));
                mma16(c[0][2*nfp],   a[0], b0a, b1a);
                mma16(c[1][2*nfp],   a[1], b0a, b1a);
                mma16(c[0][2*nfp+1], a[0], b0b, b1b);
                mma16(c[1][2*nfp+1], a[1], b0b, b1b);
            }
        }
    }

    // epilogue: direct stores, known fragment layout
    #pragma unroll
    for (int mf = 0; mf < 2; mf++) {
        #pragma unroll
        for (int nf = 0; nf < 8; nf++) {
            int m = m0 + wm*32 + mf*16 + g;       // rows m and m+8 (same 1024-block)
            int n = n0 + wn*64 + nf*8 + 2*t;
            float bv0 = sBias[n - n0], bv1 = sBias[n - n0 + 1];
            float v00 = c[mf][nf][0] + bv0, v01 = c[mf][nf][1] + bv1;   // row m
            float v10 = c[mf][nf][2] + bv0, v11 = c[mf][nf][3] + bv1;   // row m+8
            if (mode == 1) {
                *(float2*)&Cout[(size_t)m*768 + n]     = make_float2(v00, v01);
                *(float2*)&Cout[(size_t)(m+8)*768 + n] = make_float2(v10, v11);
            } else {
                int c3 = n / 768;
                int rem = n - c3*768;
                int h = rem >> 6, d = rem & 63;
                __half* dst = (c3 == 0) ? g_qh : (c3 == 1) ? g_kh : g_vh;
                int bb = m >> 10, tt = m & 1023;
                size_t rowbase = ((size_t)(bb*NHEAD + h)*SEQ + tt)*64 + d;
                *(__half2*)&dst[rowbase]        = __floats2half2_rn(v00, v01);
                *(__half2*)&dst[rowbase + 8*64] = __floats2half2_rn(v10, v11);
            }
        }
    }
}

// ---------------------------------------------------------------------------
// Flash attention, fp16 mma + ldmatrix (R11 structure: S->softmax->PV per
// iter) with a 3-stage KV ring and ONE barrier per iteration.
// grid (8 q-tiles, 48 bh), 256 thr = 8 warps x 16 q-rows.
// relT overlays stage 2's K half during the prologue (stage 2 first written
// at iter 0, after relT is consumed; ordered by the iter-0 barrier).
// ---------------------------------------------------------------------------
#define LDKH 72
#define KST (2*64*LDKH)   // halves per KV stage (K 64x72 | V 64x72)
#define CSC 0.18033688f   // 0.125 * log2(e)

__global__ __launch_bounds__(256, 2) void attn_flash(const float* __restrict__ rel_emb)
{
    extern __shared__ __align__(16) char saraw[];
    __half* stg = (__half*)saraw;               // 3 KV stages
    __half* sQ  = stg + 3*KST;                  // 128 x 72 halves
    float*  sR  = (float*)(sQ + 128*LDKH);      // 128 x 36 floats
    float*  relT = (float*)(stg + 2*KST);       // overlays stage 2 K half (9216 B)

    const int t0 = blockIdx.x * 128;
    const int bh = blockIdx.y;
    const int tid = threadIdx.x;
    const int w = tid >> 5;            // 0..7
    const int lane = tid & 31;
    const int g = lane >> 2;
    const int t = lane & 3;

    const __half* qb = g_qh + ((size_t)bh*SEQ + t0)*64;
    const __half* kb = g_kh + (size_t)bh*SEQ*64;
    const __half* vb = g_vh + (size_t)bh*SEQ*64;

    // ldmatrix lane address components (bytes)
    const int lmat = lane >> 3, lrow = lane & 7;
    const unsigned laneK = ((unsigned)((lmat >> 1)*8 + lrow))*(LDKH*2) + (unsigned)(lmat & 1)*16;
    const unsigned laneV = ((unsigned)((lmat & 1)*8 + lrow))*(LDKH*2) + (unsigned)(lmat >> 1)*16;
    const unsigned laneQ = ((unsigned)((lmat & 1)*8 + lrow))*(LDKH*2) + (unsigned)(lmat >> 1)*16;

    auto issueKV = [&](int s0, int stage) {
        __half* dK = stg + stage*KST;
        __half* dV = dK + 64*LDKH;
        #pragma unroll
        for (int u = 0; u < 2; u++) {
            int idx = tid + u*256;               // 512 x 16B per matrix
            int r = idx >> 3, c8 = idx & 7;
            cp16(&dK[r*LDKH + c8*8], &kb[(size_t)(s0 + r)*64 + c8*8]);
            cp16(&dV[r*LDKH + c8*8], &vb[(size_t)(s0 + r)*64 + c8*8]);
        }
        CP_COMMIT();
    };

    issueKV(0, 0);                                 // G1: KV stage 0
    #pragma unroll
    for (int u = 0; u < 4; u++) {                  // G2: Q (128 rows)
        int idx = tid + u*256;
        int r = idx >> 3, c8 = idx & 7;
        cp16(&sQ[r*LDKH + c8*8], &qb[(size_t)r*64 + c8*8]);
    }
    CP_COMMIT();
    issueKV(64, 1);                                // G3: KV stage 1
    // relT (transposed, conflict-free): direct loads into stage-2 K region
    for (int idx = tid; idx < 33*64; idx += 256) {
        int j = idx >> 6, d = idx & 63;
        relT[d*36 + j] = rel_emb[idx];
    }
    CP_WAIT1();                   // G1 (KV0), G2 (Q) complete
    __syncthreads();

    // rel projections: sR[r][j] = (Q[r] . rel[j]) * scale * log2e
    for (int idx = tid; idx < 128*33; idx += 256) {
        int r = idx / 33, j = idx - r*33;
        const __half* qr = &sQ[r*LDKH];
        float acc = 0.0f;
        #pragma unroll 16
        for (int d = 0; d < 64; d++)
            acc += __half2float(qr[d]) * relT[d*36 + j];
        sR[r*36 + j] = acc * CSC;
    }

    // persistent Q A-fragments (warp w: rows w*16..w*16+15)
    const int r0 = w*16 + g;
    unsigned qa[4][4];
    {
        unsigned q_s = (unsigned)__cvta_generic_to_shared(sQ);
        #pragma unroll
        for (int kc = 0; kc < 4; kc++)
            ldsm4(qa[kc][0], qa[kc][1], qa[kc][2], qa[kc][3],
                  q_s + laneQ + (unsigned)((w*16*LDKH + kc*16)*2));
    }

    const unsigned stBase = (unsigned)__cvta_generic_to_shared(stg);

    float o[8][4];
    #pragma unroll
    for (int i = 0; i < 8; i++)
        #pragma unroll
        for (int j = 0; j < 4; j++) o[i][j] = 0.0f;
    float m0v = -INFINITY, m1v = -INFINITY, l0 = 0.0f, l1 = 0.0f;

    const int rowt0 = t0 + r0, rowt1 = rowt0 + 8;

    for (int it = 0; it < 16; it++) {
        CP_WAIT1();                 // stage it resident (one commit per iter)
        __syncthreads();            // all warps done with compute(it-1); relT consumed
        if (it + 2 < 16) issueKV((it + 2)*64, (it + 2) % 3);  // overwrites stage (it-1)%3
        else CP_COMMIT();

        const unsigned kx = stBase + (unsigned)((it % 3)*KST*2);
        const unsigned vx = kx + (unsigned)(64*LDKH*2);
        const int s0 = it * 64;

        // S = Q @ K^T   (16 x 64 per warp)
        float s[8][4];
        #pragma unroll
        for (int nfp = 0; nfp < 4; nfp++) {
            s[2*nfp][0] = s[2*nfp][1] = s[2*nfp][2] = s[2*nfp][3] = 0.0f;
            s[2*nfp+1][0] = s[2*nfp+1][1] = s[2*nfp+1][2] = s[2*nfp+1][3] = 0.0f;
            #pragma unroll
            for (int kc = 0; kc < 4; kc++) {
                unsigned b0a, b1a, b0b, b1b;
                ldsm4(b0a, b1a, b0b, b1b,
                      kx + laneK + (unsigned)((nfp*16*LDKH + kc*16)*2));
                mma16(s[2*nfp],   qa[kc], b0a, b1a);
                mma16(s[2*nfp+1], qa[kc], b0b, b1b);
            }
        }

        // bias + scale (log2 domain), row maxes
        const bool uni = (s0 >= t0 + 192) || (s0 + 128 <= t0);
        float bc0 = 0.0f, bc1 = 0.0f;
        if (uni) {
            int jj = (s0 > t0) ? 32 : 0;
            bc0 = sR[r0*36 + jj];
            bc1 = sR[(r0+8)*36 + jj];
        }
        float mn0 = -INFINITY, mn1 = -INFINITY;
        #pragma unroll
        for (int nf = 0; nf < 8; nf++) {
            int cc = s0 + nf*8 + 2*t;
            if (uni) {
                s[nf][0] = s[nf][0]*CSC + bc0;
                s[nf][1] = s[nf][1]*CSC + bc0;
                s[nf][2] = s[nf][2]*CSC + bc1;
                s[nf][3] = s[nf][3]*CSC + bc1;
            } else {
                int d00 = cc - rowt0;     d00 = d00 < -16 ? -16 : (d00 > 16 ? 16 : d00);
                int d01 = cc + 1 - rowt0; d01 = d01 < -16 ? -16 : (d01 > 16 ? 16 : d01);
                int d10 = cc - rowt1;     d10 = d10 < -16 ? -16 : (d10 > 16 ? 16 : d10);
                int d11 = cc + 1 - rowt1; d11 = d11 < -16 ? -16 : (d11 > 16 ? 16 : d11);
                s[nf][0] = s[nf][0]*CSC + sR[r0*36 + d00 + 16];
                s[nf][1] = s[nf][1]*CSC + sR[r0*36 + d01 + 16];
                s[nf][2] = s[nf][2]*CSC + sR[(r0+8)*36 + d10 + 16];
                s[nf][3] = s[nf][3]*CSC + sR[(r0+8)*36 + d11 + 16];
            }
            mn0 = fmaxf(mn0, fmaxf(s[nf][0], s[nf][1]));
            mn1 = fmaxf(mn1, fmaxf(s[nf][2], s[nf][3]));
        }
        mn0 = fmaxf(mn0, __shfl_xor_sync(0xffffffffu, mn0, 1));
        mn0 = fmaxf(mn0, __shfl_xor_sync(0xffffffffu, mn0, 2));
        mn1 = fmaxf(mn1, __shfl_xor_sync(0xffffffffu, mn1, 1));
        mn1 = fmaxf(mn1, __shfl_xor_sync(0xffffffffu, mn1, 2));
        float m0n = fmaxf(m0v, mn0);
        float m1n = fmaxf(m1v, mn1);
        float a0 = ex2(m0v - m0n);
        float a1 = ex2(m1v - m1n);
        m0v = m0n; m1v = m1n;

        // P = exp2(val - m); pack straight into f16 A-operand layout (no shuffles)
        float ls0 = 0.0f, ls1 = 0.0f;
        unsigned ph[8][2];
        #pragma unroll
        for (int nf = 0; nf < 8; nf++) {
            float p00 = ex2(s[nf][0] - m0n);
            float p01 = ex2(s[nf][1] - m0n);
            float p10 = ex2(s[nf][2] - m1n);
            float p11 = ex2(s[nf][3] - m1n);
            ls0 += p00 + p01;
            ls1 += p10 + p11;
            ph[nf][0] = h2u(__floats2half2_rn(p00, p01));  // row g
            ph[nf][1] = h2u(__floats2half2_rn(p10, p11));  // row g+8
        }
        ls0 += __shfl_xor_sync(0xffffffffu, ls0, 1);
        ls0 += __shfl_xor_sync(0xffffffffu, ls0, 2);
        ls1 += __shfl_xor_sync(0xffffffffu, ls1, 1);
        ls1 += __shfl_xor_sync(0xffffffffu, ls1, 2);
        l0 = l0*a0 + ls0;
        l1 = l1*a1 + ls1;
        #pragma unroll
        for (int dn = 0; dn < 8; dn++) {
            o[dn][0] *= a0; o[dn][1] *= a0;
            o[dn][2] *= a1; o[dn][3] *= a1;
        }

        // O += P @ V   (16 x 64); V^T fragments via ldmatrix.x4.trans
        #pragma unroll
        for (int kc = 0; kc < 4; kc++) {
            unsigned a[4] = { ph[2*kc][0], ph[2*kc][1], ph[2*kc+1][0], ph[2*kc+1][1] };
            #pragma unroll
            for (int dnp = 0; dnp < 4; dnp++) {
                unsigned b0a, b1a, b0b, b1b;
                ldsm4t(b0a, b1a, b0b, b1b,
                       vx + laneV + (unsigned)((kc*16*LDKH + dnp*16)*2));
                mma16(o[2*dnp],   a, b0a, b1a);
                mma16(o[2*dnp+1], a, b0b, b1b);
            }
        }
    }

    // epilogue: normalize, write half [B,T,H*64]
    const int bb = bh / NHEAD, h = bh - bb*NHEAD;
    const float inv0 = 1.0f / l0;
    const float inv1 = 1.0f / l1;
    __half* o0 = g_attnh + ((size_t)(bb*SEQ + t0 + r0))*D_MODEL + h*64;
    __half* o1 = o0 + (size_t)8*D_MODEL;
    #pragma unroll
    for (int dn = 0; dn < 8; dn++) {
        *(__half2*)(o0 + dn*8 + 2*t) = __floats2half2_rn(o[dn][0]*inv0, o[dn][1]*inv0);
        *(__half2*)(o1 + dn*8 + 2*t) = __floats2half2_rn(o[dn][2]*inv1, o[dn][3]*inv1);
    }
}

// ---------------------------------------------------------------------------
extern "C" void kernel_launch(void* const* d_in, const int* in_sizes, int n_in,
                              void* d_out, int out_size)
{
    const float* x     = (const float*)d_in[0];
    const float* qkv_w = (const float*)d_in[1];
    const float* qkv_b = (const float*)d_in[2];
    const float* out_w = (const float*)d_in[3];
    const float* out_b = (const float*)d_in[4];
    const float* rel   = (const float*)d_in[5];
    float* out = (float*)d_out;

    (void)in_sizes; (void)n_in; (void)out_size;

    const int gemm_smem = 3*GST*2 + 128*4;                     // 111,104 B
    const int attn_smem = 3*KST*2 + 128*LDKH*2 + 128*36*4;     // 92,160 B
    cudaFuncSetAttribute(gemm_half, cudaFuncAttributeMaxDynamicSharedMemorySize, gemm_smem);
    cudaFuncSetAttribute(attn_flash, cudaFuncAttributeMaxDynamicSharedMemorySize, attn_smem);

    // 0) fp32 -> fp16 conversion pre-pass
    to_half<<<(MTOT*D_MODEL/4 + 255)/256, 256>>>(x, 0, MTOT*D_MODEL/4);
    to_half<<<(3*D_MODEL*D_MODEL/4 + 255)/256, 256>>>(qkv_w, 1, 3*D_MODEL*D_MODEL/4);
    to_half<<<(D_MODEL*D_MODEL/4 + 255)/256, 256>>>(out_w, 2, D_MODEL*D_MODEL/4);
    // 1) QKV projection -> half q/k/v [B,H,T,64]
    gemm_half<<<dim3(18, 32), 256, gemm_smem>>>(qkv_b, nullptr, 0);
    // 2) fused flash attention (3-stage ring, one barrier per iter)
    attn_flash<<<dim3(8, 48), 256, attn_smem>>>(rel);
    // 3) output projection
    gemm_half<<<dim3(6, 32), 256, gemm_smem>>>(out_b, out, 1);
}

// round 14
// speedup vs baseline: 1.2314x; 1.1772x over previous
#include <cuda_runtime.h>
#include <cuda_fp16.h>
#include <math.h>

#define D_MODEL 768
#define NHEAD 12
#define HEAD_DIM 64
#define BATCH 4
#define SEQ 1024
#define MTOT (BATCH*SEQ)

// scratch (allocation-free requirement -> device globals)
__device__ __half g_xh[MTOT*D_MODEL];
__device__ __half g_wqkvh[3*D_MODEL*D_MODEL];
__device__ __half g_wouth[D_MODEL*D_MODEL];
__device__ __half g_relh[48*64];      // rel_pos_emb as half, rows 33..47 stay zero
__device__ __half g_qh[BATCH*NHEAD*SEQ*HEAD_DIM];
__device__ __half g_kh[BATCH*NHEAD*SEQ*HEAD_DIM];
__device__ __half g_vh[BATCH*NHEAD*SEQ*HEAD_DIM];
__device__ __half g_attnh[MTOT*D_MODEL];

// ---------------------------------------------------------------------------
// helpers
// ---------------------------------------------------------------------------
__device__ __forceinline__ void cp16(void* s, const void* g) {
    unsigned sa = (unsigned)__cvta_generic_to_shared(s);
    asm volatile("cp.async.cg.shared.global [%0], [%1], 16;" :: "r"(sa), "l"(g));
}
#define CP_COMMIT() asm volatile("cp.async.commit_group;")
#define CP_WAIT1()  asm volatile("cp.async.wait_group 1;")

__device__ __forceinline__ float ex2(float x) {
    float r;
    asm("ex2.approx.ftz.f32 %0, %1;" : "=f"(r) : "f"(x));
    return r;
}

// bit-cast __half2 -> u32 (register reinterpret, no instruction)
__device__ __forceinline__ unsigned h2u(__half2 h) {
    __half2_raw hr = *(__half2_raw*)&h;
    unsigned u = (unsigned)hr.x | ((unsigned)hr.y << 16);
    return u;
}

// warp-collective 8x8 b16 matrix loads (4 matrices per call)
__device__ __forceinline__ void ldsm4(unsigned& r0, unsigned& r1, unsigned& r2,
                                      unsigned& r3, unsigned addr) {
    asm volatile("ldmatrix.sync.aligned.m8n8.x4.shared.b16 {%0,%1,%2,%3}, [%4];"
                 : "=r"(r0), "=r"(r1), "=r"(r2), "=r"(r3) : "r"(addr));
}
__device__ __forceinline__ void ldsm4t(unsigned& r0, unsigned& r1, unsigned& r2,
                                       unsigned& r3, unsigned addr) {
    asm volatile("ldmatrix.sync.aligned.m8n8.x4.trans.shared.b16 {%0,%1,%2,%3}, [%4];"
                 : "=r"(r0), "=r"(r1), "=r"(r2), "=r"(r3) : "r"(addr));
}

// mma.m16n8k16 f16 inputs, f32 accum (documented fragment layouts)
__device__ __forceinline__ void mma16(float* d, const unsigned* a, unsigned b0, unsigned b1) {
    asm volatile(
        "mma.sync.aligned.m16n8k16.row.col.f32.f16.f16.f32 "
        "{%0,%1,%2,%3}, {%4,%5,%6,%7}, {%8,%9}, {%0,%1,%2,%3};"
        : "+f"(d[0]), "+f"(d[1]), "+f"(d[2]), "+f"(d[3])
        : "r"(a[0]), "r"(a[1]), "r"(a[2]), "r"(a[3]), "r"(b0), "r"(b1));
}

// ---------------------------------------------------------------------------
// fp32 -> fp16 conversion pre-pass (which: 0=x, 1=qkv_w, 2=out_w, 3=rel)
// ---------------------------------------------------------------------------
__global__ void to_half(const float* __restrict__ src, int which, int n4)
{
    __half* dst = (which == 0) ? g_xh : (which == 1) ? g_wqkvh
                : (which == 2) ? g_wouth : g_relh;
    int i = blockIdx.x * blockDim.x + threadIdx.x;
    if (i < n4) {
        float4 v = ((const float4*)src)[i];
        __half2* d2 = (__half2*)dst;
        d2[i*2]   = __floats2half2_rn(v.x, v.y);
        d2[i*2+1] = __floats2half2_rn(v.z, v.w);
    }
}

// ---------------------------------------------------------------------------
// fp16 GEMM: C[m,n] = sum_k A[m,k]*W[n,k] + bias[n]
// Block 128x128, K-chunk 64, 3-stage cp.async pipeline (ONE sync per iter),
// 256 thr (8 warps), warp tile 32x64, operands via ldmatrix.x4.
// mode 0: A = g_xh,    epilogue -> half, scattered into g_qh/g_kh/g_vh [B,H,T,64]
// mode 1: A = g_attnh, epilogue -> f32 Cout row-major [4096,768]
// ---------------------------------------------------------------------------
#define LDH 72
#define GST (2*128*LDH)   // halves per stage (A tile + B tile)
__global__ __launch_bounds__(256, 2) void gemm_half(
    const float* __restrict__ bias,
    float* __restrict__ Cout,
    int mode)
{
    extern __shared__ __align__(16) char smraw[];
    __half* st = (__half*)smraw;                  // 3 stages x (A 128x72 | B 128x72)
    float*  sBias = (float*)(st + 3*GST);         // 128 floats

    const __half* A = (mode == 0) ? g_xh : g_attnh;
    const __half* W = (mode == 0) ? g_wqkvh : g_wouth;

    const int n0 = blockIdx.x * 128;
    const int m0 = blockIdx.y * 128;
    const int tid = threadIdx.x;
    const int warp = tid >> 5;
    const int lane = tid & 31;
    const int g = lane >> 2;
    const int t = lane & 3;
    const int wm = warp & 3;   // 4 m-slabs of 32
    const int wn = warp >> 2;  // 2 n-slabs of 64

    // ldmatrix lane address components (bytes)
    const int lmat = lane >> 3, lrow = lane & 7;
    const unsigned laneA = ((unsigned)((lmat & 1)*8 + lrow))*(LDH*2) + (unsigned)(lmat >> 1)*16;
    const unsigned laneB = ((unsigned)((lmat >> 1)*8 + lrow))*(LDH*2) + (unsigned)(lmat & 1)*16;

    auto issue = [&](int kt, int s) {
        __half* as = st + s*GST;
        __half* bs = as + 128*LDH;
        #pragma unroll
        for (int u = 0; u < 4; u++) {
            int idx = tid + u*256;               // 1024 x 16B for A
            int r = idx >> 3, c8 = idx & 7;
            cp16(&as[r*LDH + c8*8], &A[(size_t)(m0 + r)*768 + kt + c8*8]);
        }
        #pragma unroll
        for (int u = 0; u < 4; u++) {
            int idx = tid + u*256;
            int r = idx >> 3, c8 = idx & 7;
            cp16(&bs[r*LDH + c8*8], &W[(size_t)(n0 + r)*768 + kt + c8*8]);
        }
        CP_COMMIT();
    };

    issue(0, 0);
    issue(64, 1);
    if (tid < 128) sBias[tid] = bias[n0 + tid];

    const unsigned stBase = (unsigned)__cvta_generic_to_shared(st);

    float c[2][8][4];
    #pragma unroll
    for (int mf = 0; mf < 2; mf++)
        #pragma unroll
        for (int nf = 0; nf < 8; nf++)
            #pragma unroll
            for (int e = 0; e < 4; e++) c[mf][nf][e] = 0.0f;

    for (int it = 0; it < 12; it++) {
        CP_WAIT1();                 // stage it resident
        __syncthreads();            // all warps done with compute(it-1)
        if (it + 2 < 12) issue((it + 2)*64, (it + 2) % 3);   // overwrites buf (it-1)%3: safe
        else CP_COMMIT();

        const unsigned as_s = stBase + (unsigned)((it % 3)*GST*2);
        const unsigned bs_s = as_s + 128*LDH*2;

        #pragma unroll
        for (int kc = 0; kc < 4; kc++) {
            unsigned a[2][4];
            #pragma unroll
            for (int mf = 0; mf < 2; mf++)
                ldsm4(a[mf][0], a[mf][1], a[mf][2], a[mf][3],
                      as_s + laneA + (unsigned)(((wm*32 + mf*16)*LDH + kc*16)*2));
            #pragma unroll
            for (int nfp = 0; nfp < 4; nfp++) {
                unsigned b0a, b1a, b0b, b1b;
                ldsm4(b0a, b1a, b0b, b1b,
                      bs_s + laneB + (unsigned)(((wn*64 + nfp*16)*LDH + kc*16)*2));
                mma16(c[0][2*nfp],   a[0], b0a, b1a);
                mma16(c[1][2*nfp],   a[1], b0a, b1a);
                mma16(c[0][2*nfp+1], a[0], b0b, b1b);
                mma16(c[1][2*nfp+1], a[1], b0b, b1b);
            }
        }
    }

    // epilogue: direct stores, known fragment layout
    #pragma unroll
    for (int mf = 0; mf < 2; mf++) {
        #pragma unroll
        for (int nf = 0; nf < 8; nf++) {
            int m = m0 + wm*32 + mf*16 + g;       // rows m and m+8 (same 1024-block)
            int n = n0 + wn*64 + nf*8 + 2*t;
            float bv0 = sBias[n - n0], bv1 = sBias[n - n0 + 1];
            float v00 = c[mf][nf][0] + bv0, v01 = c[mf][nf][1] + bv1;   // row m
            float v10 = c[mf][nf][2] + bv0, v11 = c[mf][nf][3] + bv1;   // row m+8
            if (mode == 1) {
                *(float2*)&Cout[(size_t)m*768 + n]     = make_float2(v00, v01);
                *(float2*)&Cout[(size_t)(m+8)*768 + n] = make_float2(v10, v11);
            } else {
                int c3 = n / 768;
                int rem = n - c3*768;
                int h = rem >> 6, d = rem & 63;
                __half* dst = (c3 == 0) ? g_qh : (c3 == 1) ? g_kh : g_vh;
                int bb = m >> 10, tt = m & 1023;
                size_t rowbase = ((size_t)(bb*NHEAD + h)*SEQ + tt)*64 + d;
                *(__half2*)&dst[rowbase]        = __floats2half2_rn(v00, v01);
                *(__half2*)&dst[rowbase + 8*64] = __floats2half2_rn(v10, v11);
            }
        }
    }
}

// ---------------------------------------------------------------------------
// Flash attention, fp16 mma + ldmatrix; 3-stage KV ring, one barrier/iter.
// grid (8 q-tiles, 48 bh), 256 thr = 8 warps x 16 q-rows.
// Rel projections R = Q @ rel^T computed via MMA (rel as half, K-major, in
// the stage-2 K region during the prologue) -- replaces the scalar dot loop.
// ---------------------------------------------------------------------------
#define LDKH 72
#define KST (2*64*LDKH)   // halves per KV stage (K 64x72 | V 64x72)
#define CSC 0.18033688f   // 0.125 * log2(e)

__global__ __launch_bounds__(256, 2) void attn_flash()
{
    extern __shared__ __align__(16) char saraw[];
    __half* stg = (__half*)saraw;               // 3 KV stages
    __half* sQ  = stg + 3*KST;                  // 128 x 72 halves
    float*  sR  = (float*)(sQ + 128*LDKH);      // 128 x 36 floats
    __half* sRel = stg + 2*KST;                 // overlays stage 2 K half: 48 x 72

    const int t0 = blockIdx.x * 128;
    const int bh = blockIdx.y;
    const int tid = threadIdx.x;
    const int w = tid >> 5;            // 0..7
    const int lane = tid & 31;
    const int g = lane >> 2;
    const int t = lane & 3;

    const __half* qb = g_qh + ((size_t)bh*SEQ + t0)*64;
    const __half* kb = g_kh + (size_t)bh*SEQ*64;
    const __half* vb = g_vh + (size_t)bh*SEQ*64;

    // ldmatrix lane address components (bytes)
    const int lmat = lane >> 3, lrow = lane & 7;
    const unsigned laneK = ((unsigned)((lmat >> 1)*8 + lrow))*(LDKH*2) + (unsigned)(lmat & 1)*16;
    const unsigned laneV = ((unsigned)((lmat & 1)*8 + lrow))*(LDKH*2) + (unsigned)(lmat >> 1)*16;
    const unsigned laneQ = ((unsigned)((lmat & 1)*8 + lrow))*(LDKH*2) + (unsigned)(lmat >> 1)*16;

    auto issueKV = [&](int s0, int stage) {
        __half* dK = stg + stage*KST;
        __half* dV = dK + 64*LDKH;
        #pragma unroll
        for (int u = 0; u < 2; u++) {
            int idx = tid + u*256;               // 512 x 16B per matrix
            int r = idx >> 3, c8 = idx & 7;
            cp16(&dK[r*LDKH + c8*8], &kb[(size_t)(s0 + r)*64 + c8*8]);
            cp16(&dV[r*LDKH + c8*8], &vb[(size_t)(s0 + r)*64 + c8*8]);
        }
        CP_COMMIT();
    };

    issueKV(0, 0);                                 // G1: KV stage 0
    // G2: Q (128 rows) + rel (48 rows, half, K-major) in one group
    #pragma unroll
    for (int u = 0; u < 4; u++) {
        int idx = tid + u*256;
        int r = idx >> 3, c8 = idx & 7;
        cp16(&sQ[r*LDKH + c8*8], &qb[(size_t)r*64 + c8*8]);
    }
    for (int idx = tid; idx < 48*8; idx += 256) {  // 384 x 16B
        int r = idx >> 3, c8 = idx & 7;
        cp16(&sRel[r*LDKH + c8*8], &g_relh[r*64 + c8*8]);
    }
    CP_COMMIT();
    issueKV(64, 1);                                // G3: KV stage 1
    CP_WAIT1();                   // G1 (KV0), G2 (Q+rel) complete
    __syncthreads();

    // persistent Q A-fragments (warp w: rows w*16..w*16+15)
    const int r0 = w*16 + g;
    unsigned qa[4][4];
    {
        unsigned q_s = (unsigned)__cvta_generic_to_shared(sQ);
        #pragma unroll
        for (int kc = 0; kc < 4; kc++)
            ldsm4(qa[kc][0], qa[kc][1], qa[kc][2], qa[kc][3],
                  q_s + laneQ + (unsigned)((w*16*LDKH + kc*16)*2));
    }

    // R = Q @ rel^T via MMA (48 cols, only j<36 stored; j in [33,48) are zero)
    {
        const unsigned rel_s = (unsigned)__cvta_generic_to_shared(sRel);
        float rr[6][4];
        #pragma unroll
        for (int nfp = 0; nfp < 3; nfp++) {
            rr[2*nfp][0] = rr[2*nfp][1] = rr[2*nfp][2] = rr[2*nfp][3] = 0.0f;
            rr[2*nfp+1][0] = rr[2*nfp+1][1] = rr[2*nfp+1][2] = rr[2*nfp+1][3] = 0.0f;
            #pragma unroll
            for (int kc = 0; kc < 4; kc++) {
                unsigned b0a, b1a, b0b, b1b;
                ldsm4(b0a, b1a, b0b, b1b,
                      rel_s + laneK + (unsigned)((nfp*16*LDKH + kc*16)*2));
                mma16(rr[2*nfp],   qa[kc], b0a, b1a);
                mma16(rr[2*nfp+1], qa[kc], b0b, b1b);
            }
        }
        #pragma unroll
        for (int nf = 0; nf < 5; nf++) {
            int col = nf*8 + 2*t;
            if (col < 36) {
                sR[r0*36 + col]         = rr[nf][0]*CSC;
                sR[r0*36 + col + 1]     = rr[nf][1]*CSC;
                sR[(r0+8)*36 + col]     = rr[nf][2]*CSC;
                sR[(r0+8)*36 + col + 1] = rr[nf][3]*CSC;
            }
        }
    }
    // sR visibility + sRel reuse are both covered by the iter-0 barrier below.

    const unsigned stBase = (unsigned)__cvta_generic_to_shared(stg);

    float o[8][4];
    #pragma unroll
    for (int i = 0; i < 8; i++)
        #pragma unroll
        for (int j = 0; j < 4; j++) o[i][j] = 0.0f;
    float m0v = -INFINITY, m1v = -INFINITY, l0 = 0.0f, l1 = 0.0f;

    const int rowt0 = t0 + r0, rowt1 = rowt0 + 8;

    for (int it = 0; it < 16; it++) {
        CP_WAIT1();                 // stage it resident (one commit per iter)
        __syncthreads();            // compute(it-1) done; prologue sR/sRel settled
        if (it + 2 < 16) issueKV((it + 2)*64, (it + 2) % 3);  // overwrites stage (it-1)%3
        else CP_COMMIT();

        const unsigned kx = stBase + (unsigned)((it % 3)*KST*2);
        const unsigned vx = kx + (unsigned)(64*LDKH*2);
        const int s0 = it * 64;

        // S = Q @ K^T   (16 x 64 per warp)
        float s[8][4];
        #pragma unroll
        for (int nfp = 0; nfp < 4; nfp++) {
            s[2*nfp][0] = s[2*nfp][1] = s[2*nfp][2] = s[2*nfp][3] = 0.0f;
            s[2*nfp+1][0] = s[2*nfp+1][1] = s[2*nfp+1][2] = s[2*nfp+1][3] = 0.0f;
            #pragma unroll
            for (int kc = 0; kc < 4; kc++) {
                unsigned b0a, b1a, b0b, b1b;
                ldsm4(b0a, b1a, b0b, b1b,
                      kx + laneK + (unsigned)((nfp*16*LDKH + kc*16)*2));
                mma16(s[2*nfp],   qa[kc], b0a, b1a);
                mma16(s[2*nfp+1], qa[kc], b0b, b1b);
            }
        }

        // bias + scale (log2 domain), row maxes
        const bool uni = (s0 >= t0 + 192) || (s0 + 128 <= t0);
        float bc0 = 0.0f, bc1 = 0.0f;
        if (uni) {
            int jj = (s0 > t0) ? 32 : 0;
            bc0 = sR[r0*36 + jj];
            bc1 = sR[(r0+8)*36 + jj];
        }
        float mn0 = -INFINITY, mn1 = -INFINITY;
        #pragma unroll
        for (int nf = 0; nf < 8; nf++) {
            int cc = s0 + nf*8 + 2*t;
            if (uni) {
                s[nf][0] = s[nf][0]*CSC + bc0;
                s[nf][1] = s[nf][1]*CSC + bc0;
                s[nf][2] = s[nf][2]*CSC + bc1;
                s[nf][3] = s[nf][3]*CSC + bc1;
            } else {
                int d00 = cc - rowt0;     d00 = d00 < -16 ? -16 : (d00 > 16 ? 16 : d00);
                int d01 = cc + 1 - rowt0; d01 = d01 < -16 ? -16 : (d01 > 16 ? 16 : d01);
                int d10 = cc - rowt1;     d10 = d10 < -16 ? -16 : (d10 > 16 ? 16 : d10);
                int d11 = cc + 1 - rowt1; d11 = d11 < -16 ? -16 : (d11 > 16 ? 16 : d11);
                s[nf][0] = s[nf][0]*CSC + sR[r0*36 + d00 + 16];
                s[nf][1] = s[nf][1]*CSC + sR[r0*36 + d01 + 16];
                s[nf][2] = s[nf][2]*CSC + sR[(r0+8)*36 + d10 + 16];
                s[nf][3] = s[nf][3]*CSC + sR[(r0+8)*36 + d11 + 16];
            }
            mn0 = fmaxf(mn0, fmaxf(s[nf][0], s[nf][1]));
            mn1 = fmaxf(mn1, fmaxf(s[nf][2], s[nf][3]));
        }
        mn0 = fmaxf(mn0, __shfl_xor_sync(0xffffffffu, mn0, 1));
        mn0 = fmaxf(mn0, __shfl_xor_sync(0xffffffffu, mn0, 2));
        mn1 = fmaxf(mn1, __shfl_xor_sync(0xffffffffu, mn1, 1));
        mn1 = fmaxf(mn1, __shfl_xor_sync(0xffffffffu, mn1, 2));
        float m0n = fmaxf(m0v, mn0);
        float m1n = fmaxf(m1v, mn1);
        float a0 = ex2(m0v - m0n);
        float a1 = ex2(m1v - m1n);
        m0v = m0n; m1v = m1n;

        // P = exp2(val - m); pack straight into f16 A-operand layout (no shuffles)
        float ls0 = 0.0f, ls1 = 0.0f;
        unsigned ph[8][2];
        #pragma unroll
        for (int nf = 0; nf < 8; nf++) {
            float p00 = ex2(s[nf][0] - m0n);
            float p01 = ex2(s[nf][1] - m0n);
            float p10 = ex2(s[nf][2] - m1n);
            float p11 = ex2(s[nf][3] - m1n);
            ls0 += p00 + p01;
            ls1 += p10 + p11;
            ph[nf][0] = h2u(__floats2half2_rn(p00, p01));  // row g
            ph[nf][1] = h2u(__floats2half2_rn(p10, p11));  // row g+8
        }
        ls0 += __shfl_xor_sync(0xffffffffu, ls0, 1);
        ls0 += __shfl_xor_sync(0xffffffffu, ls0, 2);
        ls1 += __shfl_xor_sync(0xffffffffu, ls1, 1);
        ls1 += __shfl_xor_sync(0xffffffffu, ls1, 2);
        l0 = l0*a0 + ls0;
        l1 = l1*a1 + ls1;
        #pragma unroll
        for (int dn = 0; dn < 8; dn++) {
            o[dn][0] *= a0; o[dn][1] *= a0;
            o[dn][2] *= a1; o[dn][3] *= a1;
        }

        // O += P @ V   (16 x 64); V^T fragments via ldmatrix.x4.trans
        #pragma unroll
        for (int kc = 0; kc < 4; kc++) {
            unsigned a[4] = { ph[2*kc][0], ph[2*kc][1], ph[2*kc+1][0], ph[2*kc+1][1] };
            #pragma unroll
            for (int dnp = 0; dnp < 4; dnp++) {
                unsigned b0a, b1a, b0b, b1b;
                ldsm4t(b0a, b1a, b0b, b1b,
                       vx + laneV + (unsigned)((kc*16*LDKH + dnp*16)*2));
                mma16(o[2*dnp],   a, b0a, b1a);
                mma16(o[2*dnp+1], a, b0b, b1b);
            }
        }
    }

    // epilogue: normalize, write half [B,T,H*64]
    const int bb = bh / NHEAD, h = bh - bb*NHEAD;
    const float inv0 = 1.0f / l0;
    const float inv1 = 1.0f / l1;
    __half* o0 = g_attnh + ((size_t)(bb*SEQ + t0 + r0))*D_MODEL + h*64;
    __half* o1 = o0 + (size_t)8*D_MODEL;
    #pragma unroll
    for (int dn = 0; dn < 8; dn++) {
        *(__half2*)(o0 + dn*8 + 2*t) = __floats2half2_rn(o[dn][0]*inv0, o[dn][1]*inv0);
        *(__half2*)(o1 + dn*8 + 2*t) = __floats2half2_rn(o[dn][2]*inv1, o[dn][3]*inv1);
    }
}

// ---------------------------------------------------------------------------
extern "C" void kernel_launch(void* const* d_in, const int* in_sizes, int n_in,
                              void* d_out, int out_size)
{
    const float* x     = (const float*)d_in[0];
    const float* qkv_w = (const float*)d_in[1];
    const float* qkv_b = (const float*)d_in[2];
    const float* out_w = (const float*)d_in[3];
    const float* out_b = (const float*)d_in[4];
    const float* rel   = (const float*)d_in[5];
    float* out = (float*)d_out;

    (void)in_sizes; (void)n_in; (void)out_size;

    const int gemm_smem = 3*GST*2 + 128*4;                     // 111,104 B
    const int attn_smem = 3*KST*2 + 128*LDKH*2 + 128*36*4;     // 92,160 B
    cudaFuncSetAttribute(gemm_half, cudaFuncAttributeMaxDynamicSharedMemorySize, gemm_smem);
    cudaFuncSetAttribute(attn_flash, cudaFuncAttributeMaxDynamicSharedMemorySize, attn_smem);

    // 0) fp32 -> fp16 conversion pre-pass
    to_half<<<(MTOT*D_MODEL/4 + 255)/256, 256>>>(x, 0, MTOT*D_MODEL/4);
    to_half<<<(3*D_MODEL*D_MODEL/4 + 255)/256, 256>>>(qkv_w, 1, 3*D_MODEL*D_MODEL/4);
    to_half<<<(D_MODEL*D_MODEL/4 + 255)/256, 256>>>(out_w, 2, D_MODEL*D_MODEL/4);
    to_half<<<(33*64/4 + 255)/256, 256>>>(rel, 3, 33*64/4);
    // 1) QKV projection -> half q/k/v [B,H,T,64]
    gemm_half<<<dim3(18, 32), 256, gemm_smem>>>(qkv_b, nullptr, 0);
    // 2) fused flash attention (rel projections via MMA)
    attn_flash<<<dim3(8, 48), 256, attn_smem>>>();
    // 3) output projection
    gemm_half<<<dim3(6, 32), 256, gemm_smem>>>(out_b, out, 1);
}

// round 15
// speedup vs baseline: 1.3006x; 1.0562x over previous
#include <cuda_runtime.h>
#include <cuda_fp16.h>
#include <math.h>

#define D_MODEL 768
#define NHEAD 12
#define HEAD_DIM 64
#define BATCH 4
#define SEQ 1024
#define MTOT (BATCH*SEQ)

// scratch (allocation-free requirement -> device globals)
__device__ __half g_xh[MTOT*D_MODEL];
__device__ __half g_wqkvh[3*D_MODEL*D_MODEL];
__device__ __half g_wouth[D_MODEL*D_MODEL];
__device__ __half g_relh[48*64];      // rel_pos_emb as half, rows 33..47 stay zero
__device__ __half g_qh[BATCH*NHEAD*SEQ*HEAD_DIM];
__device__ __half g_kh[BATCH*NHEAD*SEQ*HEAD_DIM];
__device__ __half g_vh[BATCH*NHEAD*SEQ*HEAD_DIM];
__device__ __half g_attnh[MTOT*D_MODEL];

#define CSC 0.18033688f   // 0.125 * log2(e)  (folded into q at QKV epilogue)

// ---------------------------------------------------------------------------
// helpers
// ---------------------------------------------------------------------------
__device__ __forceinline__ void cp16(void* s, const void* g) {
    unsigned sa = (unsigned)__cvta_generic_to_shared(s);
    asm volatile("cp.async.cg.shared.global [%0], [%1], 16;" :: "r"(sa), "l"(g));
}
#define CP_COMMIT() asm volatile("cp.async.commit_group;")
#define CP_WAIT1()  asm volatile("cp.async.wait_group 1;")

__device__ __forceinline__ float ex2(float x) {
    float r;
    asm("ex2.approx.ftz.f32 %0, %1;" : "=f"(r) : "f"(x));
    return r;
}

// bit-cast __half2 -> u32 (register reinterpret, no instruction)
__device__ __forceinline__ unsigned h2u(__half2 h) {
    __half2_raw hr = *(__half2_raw*)&h;
    unsigned u = (unsigned)hr.x | ((unsigned)hr.y << 16);
    return u;
}

// warp-collective 8x8 b16 matrix loads (4 matrices per call)
__device__ __forceinline__ void ldsm4(unsigned& r0, unsigned& r1, unsigned& r2,
                                      unsigned& r3, unsigned addr) {
    asm volatile("ldmatrix.sync.aligned.m8n8.x4.shared.b16 {%0,%1,%2,%3}, [%4];"
                 : "=r"(r0), "=r"(r1), "=r"(r2), "=r"(r3) : "r"(addr));
}
__device__ __forceinline__ void ldsm4t(unsigned& r0, unsigned& r1, unsigned& r2,
                                       unsigned& r3, unsigned addr) {
    asm volatile("ldmatrix.sync.aligned.m8n8.x4.trans.shared.b16 {%0,%1,%2,%3}, [%4];"
                 : "=r"(r0), "=r"(r1), "=r"(r2), "=r"(r3) : "r"(addr));
}

// mma.m16n8k16 f16 inputs, f32 accum (documented fragment layouts)
__device__ __forceinline__ void mma16(float* d, const unsigned* a, unsigned b0, unsigned b1) {
    asm volatile(
        "mma.sync.aligned.m16n8k16.row.col.f32.f16.f16.f32 "
        "{%0,%1,%2,%3}, {%4,%5,%6,%7}, {%8,%9}, {%0,%1,%2,%3};"
        : "+f"(d[0]), "+f"(d[1]), "+f"(d[2]), "+f"(d[3])
        : "r"(a[0]), "r"(a[1]), "r"(a[2]), "r"(a[3]), "r"(b0), "r"(b1));
}

// ---------------------------------------------------------------------------
// single fp32 -> fp16 conversion pre-pass for all inputs (one launch)
// segments (in float4 units): x | qkv_w | out_w | rel
// ---------------------------------------------------------------------------
#define N4_X   (MTOT*D_MODEL/4)              // 786432
#define N4_QW  (3*D_MODEL*D_MODEL/4)         // 442368
#define N4_OW  (D_MODEL*D_MODEL/4)           // 147456
#define N4_REL (33*64/4)                     // 528
#define N4_ALL (N4_X + N4_QW + N4_OW + N4_REL)

__global__ void to_half_all(const float* __restrict__ x,
                            const float* __restrict__ qw,
                            const float* __restrict__ ow,
                            const float* __restrict__ rel)
{
    int i = blockIdx.x * blockDim.x + threadIdx.x;
    if (i >= N4_ALL) return;
    const float* src;
    __half2* dst;
    int off;
    if (i < N4_X)                        { src = x;   dst = (__half2*)g_xh;    off = i; }
    else if (i < N4_X + N4_QW)           { src = qw;  dst = (__half2*)g_wqkvh; off = i - N4_X; }
    else if (i < N4_X + N4_QW + N4_OW)   { src = ow;  dst = (__half2*)g_wouth; off = i - N4_X - N4_QW; }
    else                                 { src = rel; dst = (__half2*)g_relh;  off = i - N4_X - N4_QW - N4_OW; }
    float4 v = ((const float4*)src)[off];
    dst[off*2]   = __floats2half2_rn(v.x, v.y);
    dst[off*2+1] = __floats2half2_rn(v.z, v.w);
}

// ---------------------------------------------------------------------------
// fp16 GEMM: C[m,n] = sum_k A[m,k]*W[n,k] + bias[n]
// Block 128x128, K-chunk 64, 3-stage cp.async pipeline (ONE sync per iter),
// 256 thr (8 warps), warp tile 32x64, operands via ldmatrix.x4.
// mode 0: A = g_xh,    epilogue -> half, scattered into g_qh/g_kh/g_vh; q pre-scaled by CSC
// mode 1: A = g_attnh, epilogue -> f32 Cout row-major [4096,768]
// ---------------------------------------------------------------------------
#define LDH 72
#define GST (2*128*LDH)   // halves per stage (A tile + B tile)
__global__ __launch_bounds__(256, 2) void gemm_half(
    const float* __restrict__ bias,
    float* __restrict__ Cout,
    int mode)
{
    extern __shared__ __align__(16) char smraw[];
    __half* st = (__half*)smraw;                  // 3 stages x (A 128x72 | B 128x72)
    float*  sBias = (float*)(st + 3*GST);         // 128 floats

    const __half* A = (mode == 0) ? g_xh : g_attnh;
    const __half* W = (mode == 0) ? g_wqkvh : g_wouth;

    const int n0 = blockIdx.x * 128;
    const int m0 = blockIdx.y * 128;
    const int tid = threadIdx.x;
    const int warp = tid >> 5;
    const int lane = tid & 31;
    const int g = lane >> 2;
    const int t = lane & 3;
    const int wm = warp & 3;   // 4 m-slabs of 32
    const int wn = warp >> 2;  // 2 n-slabs of 64

    // ldmatrix lane address components (bytes)
    const int lmat = lane >> 3, lrow = lane & 7;
    const unsigned laneA = ((unsigned)((lmat & 1)*8 + lrow))*(LDH*2) + (unsigned)(lmat >> 1)*16;
    const unsigned laneB = ((unsigned)((lmat >> 1)*8 + lrow))*(LDH*2) + (unsigned)(lmat & 1)*16;

    auto issue = [&](int kt, int s) {
        __half* as = st + s*GST;
        __half* bs = as + 128*LDH;
        #pragma unroll
        for (int u = 0; u < 4; u++) {
            int idx = tid + u*256;               // 1024 x 16B for A
            int r = idx >> 3, c8 = idx & 7;
            cp16(&as[r*LDH + c8*8], &A[(size_t)(m0 + r)*768 + kt + c8*8]);
        }
        #pragma unroll
        for (int u = 0; u < 4; u++) {
            int idx = tid + u*256;
            int r = idx >> 3, c8 = idx & 7;
            cp16(&bs[r*LDH + c8*8], &W[(size_t)(n0 + r)*768 + kt + c8*8]);
        }
        CP_COMMIT();
    };

    issue(0, 0);
    issue(64, 1);
    if (tid < 128) sBias[tid] = bias[n0 + tid];

    const unsigned stBase = (unsigned)__cvta_generic_to_shared(st);

    float c[2][8][4];
    #pragma unroll
    for (int mf = 0; mf < 2; mf++)
        #pragma unroll
        for (int nf = 0; nf < 8; nf++)
            #pragma unroll
            for (int e = 0; e < 4; e++) c[mf][nf][e] = 0.0f;

    for (int it = 0; it < 12; it++) {
        CP_WAIT1();                 // stage it resident
        __syncthreads();            // all warps done with compute(it-1)
        if (it + 2 < 12) issue((it + 2)*64, (it + 2) % 3);   // overwrites buf (it-1)%3: safe
        else CP_COMMIT();

        const unsigned as_s = stBase + (unsigned)((it % 3)*GST*2);
        const unsigned bs_s = as_s + 128*LDH*2;

        #pragma unroll
        for (int kc = 0; kc < 4; kc++) {
            unsigned a[2][4];
            #pragma unroll
            for (int mf = 0; mf < 2; mf++)
                ldsm4(a[mf][0], a[mf][1], a[mf][2], a[mf][3],
                      as_s + laneA + (unsigned)(((wm*32 + mf*16)*LDH + kc*16)*2));
            #pragma unroll
            for (int nfp = 0; nfp < 4; nfp++) {
                unsigned b0a, b1a, b0b, b1b;
                ldsm4(b0a, b1a, b0b, b1b,
                      bs_s + laneB + (unsigned)(((wn*64 + nfp*16)*LDH + kc*16)*2));
                mma16(c[0][2*nfp],   a[0], b0a, b1a);
                mma16(c[1][2*nfp],   a[1], b0a, b1a);
                mma16(c[0][2*nfp+1], a[0], b0b, b1b);
                mma16(c[1][2*nfp+1], a[1], b0b, b1b);
            }
        }
    }

    // epilogue: direct stores, known fragment layout
    #pragma unroll
    for (int mf = 0; mf < 2; mf++) {
        #pragma unroll
        for (int nf = 0; nf < 8; nf++) {
            int m = m0 + wm*32 + mf*16 + g;       // rows m and m+8 (same 1024-block)
            int n = n0 + wn*64 + nf*8 + 2*t;
            float bv0 = sBias[n - n0], bv1 = sBias[n - n0 + 1];
            float v00 = c[mf][nf][0] + bv0, v01 = c[mf][nf][1] + bv1;   // row m
            float v10 = c[mf][nf][2] + bv0, v11 = c[mf][nf][3] + bv1;   // row m+8
            if (mode == 1) {
                *(float2*)&Cout[(size_t)m*768 + n]     = make_float2(v00, v01);
                *(float2*)&Cout[(size_t)(m+8)*768 + n] = make_float2(v10, v11);
            } else {
                int c3 = n / 768;
                int rem = n - c3*768;
                int h = rem >> 6, d = rem & 63;
                __half* dst = (c3 == 0) ? g_qh : (c3 == 1) ? g_kh : g_vh;
                if (c3 == 0) {  // pre-scale q by CSC (log2-domain softmax)
                    v00 *= CSC; v01 *= CSC; v10 *= CSC; v11 *= CSC;
                }
                int bb = m >> 10, tt = m & 1023;
                size_t rowbase = ((size_t)(bb*NHEAD + h)*SEQ + tt)*64 + d;
                *(__half2*)&dst[rowbase]        = __floats2half2_rn(v00, v01);
                *(__half2*)&dst[rowbase + 8*64] = __floats2half2_rn(v10, v11);
            }
        }
    }
}

// ---------------------------------------------------------------------------
// Flash attention, fp16 mma + ldmatrix; 3-stage KV ring, one barrier/iter.
// grid (8 q-tiles, 48 bh), 256 thr = 8 warps x 16 q-rows.
// Q pre-scaled by CSC -> S MMAs emit log2-domain scores; rel bias seeded into
// the S accumulators BEFORE the MMAs; ballot-skip of O rescale when no max moved.
// ---------------------------------------------------------------------------
#define LDKH 72
#define KST (2*64*LDKH)   // halves per KV stage (K 64x72 | V 64x72)

__global__ __launch_bounds__(256, 2) void attn_flash()
{
    extern __shared__ __align__(16) char saraw[];
    __half* stg = (__half*)saraw;               // 3 KV stages
    __half* sQ  = stg + 3*KST;                  // 128 x 72 halves
    float*  sR  = (float*)(sQ + 128*LDKH);      // 128 x 36 floats (pre-scaled bias)
    __half* sRel = stg + 2*KST;                 // overlays stage 2 K half: 48 x 72

    const int t0 = blockIdx.x * 128;
    const int bh = blockIdx.y;
    const int tid = threadIdx.x;
    const int w = tid >> 5;            // 0..7
    const int lane = tid & 31;
    const int g = lane >> 2;
    const int t = lane & 3;

    const __half* qb = g_qh + ((size_t)bh*SEQ + t0)*64;
    const __half* kb = g_kh + (size_t)bh*SEQ*64;
    const __half* vb = g_vh + (size_t)bh*SEQ*64;

    // ldmatrix lane address components (bytes)
    const int lmat = lane >> 3, lrow = lane & 7;
    const unsigned laneK = ((unsigned)((lmat >> 1)*8 + lrow))*(LDKH*2) + (unsigned)(lmat & 1)*16;
    const unsigned laneV = ((unsigned)((lmat & 1)*8 + lrow))*(LDKH*2) + (unsigned)(lmat >> 1)*16;
    const unsigned laneQ = ((unsigned)((lmat & 1)*8 + lrow))*(LDKH*2) + (unsigned)(lmat >> 1)*16;

    auto issueKV = [&](int s0, int stage) {
        __half* dK = stg + stage*KST;
        __half* dV = dK + 64*LDKH;
        #pragma unroll
        for (int u = 0; u < 2; u++) {
            int idx = tid + u*256;               // 512 x 16B per matrix
            int r = idx >> 3, c8 = idx & 7;
            cp16(&dK[r*LDKH + c8*8], &kb[(size_t)(s0 + r)*64 + c8*8]);
            cp16(&dV[r*LDKH + c8*8], &vb[(size_t)(s0 + r)*64 + c8*8]);
        }
        CP_COMMIT();
    };

    issueKV(0, 0);                                 // G1: KV stage 0
    // G2: Q (128 rows) + rel (48 rows, half, K-major) in one group
    #pragma unroll
    for (int u = 0; u < 4; u++) {
        int idx = tid + u*256;
        int r = idx >> 3, c8 = idx & 7;
        cp16(&sQ[r*LDKH + c8*8], &qb[(size_t)r*64 + c8*8]);
    }
    for (int idx = tid; idx < 48*8; idx += 256) {  // 384 x 16B
        int r = idx >> 3, c8 = idx & 7;
        cp16(&sRel[r*LDKH + c8*8], &g_relh[r*64 + c8*8]);
    }
    CP_COMMIT();
    issueKV(64, 1);                                // G3: KV stage 1
    CP_WAIT1();                   // G1 (KV0), G2 (Q+rel) complete
    __syncthreads();

    // persistent Q A-fragments (warp w: rows w*16..w*16+15); q already CSC-scaled
    const int r0 = w*16 + g;
    unsigned qa[4][4];
    {
        unsigned q_s = (unsigned)__cvta_generic_to_shared(sQ);
        #pragma unroll
        for (int kc = 0; kc < 4; kc++)
            ldsm4(qa[kc][0], qa[kc][1], qa[kc][2], qa[kc][3],
                  q_s + laneQ + (unsigned)((w*16*LDKH + kc*16)*2));
    }

    // R = Q @ rel^T via MMA (already CSC-scaled through q); store j<36
    {
        const unsigned rel_s = (unsigned)__cvta_generic_to_shared(sRel);
        float rr[6][4];
        #pragma unroll
        for (int nfp = 0; nfp < 3; nfp++) {
            rr[2*nfp][0] = rr[2*nfp][1] = rr[2*nfp][2] = rr[2*nfp][3] = 0.0f;
            rr[2*nfp+1][0] = rr[2*nfp+1][1] = rr[2*nfp+1][2] = rr[2*nfp+1][3] = 0.0f;
            #pragma unroll
            for (int kc = 0; kc < 4; kc++) {
                unsigned b0a, b1a, b0b, b1b;
                ldsm4(b0a, b1a, b0b, b1b,
                      rel_s + laneK + (unsigned)((nfp*16*LDKH + kc*16)*2));
                mma16(rr[2*nfp],   qa[kc], b0a, b1a);
                mma16(rr[2*nfp+1], qa[kc], b0b, b1b);
            }
        }
        #pragma unroll
        for (int nf = 0; nf < 5; nf++) {
            int col = nf*8 + 2*t;
            if (col < 36) {
                sR[r0*36 + col]         = rr[nf][0];
                sR[r0*36 + col + 1]     = rr[nf][1];
                sR[(r0+8)*36 + col]     = rr[nf][2];
                sR[(r0+8)*36 + col + 1] = rr[nf][3];
            }
        }
    }
    // sR visibility + sRel reuse are both covered by the iter-0 barrier below.

    const unsigned stBase = (unsigned)__cvta_generic_to_shared(stg);

    float o[8][4];
    #pragma unroll
    for (int i = 0; i < 8; i++)
        #pragma unroll
        for (int j = 0; j < 4; j++) o[i][j] = 0.0f;
    float m0v = -INFINITY, m1v = -INFINITY, l0 = 0.0f, l1 = 0.0f;

    const int rowt0 = t0 + r0, rowt1 = rowt0 + 8;

    for (int it = 0; it < 16; it++) {
        CP_WAIT1();                 // stage it resident (one commit per iter)
        __syncthreads();            // compute(it-1) done; prologue sR/sRel settled
        if (it + 2 < 16) issueKV((it + 2)*64, (it + 2) % 3);  // overwrites stage (it-1)%3
        else CP_COMMIT();

        const unsigned kx = stBase + (unsigned)((it % 3)*KST*2);
        const unsigned vx = kx + (unsigned)(64*LDKH*2);
        const int s0 = it * 64;

        // seed S accumulators with the rel bias (log2 domain), then MMA
        float s[8][4];
        const bool uni = (s0 >= t0 + 192) || (s0 + 128 <= t0);
        if (uni) {
            int jj = (s0 > t0) ? 32 : 0;
            float bc0 = sR[r0*36 + jj];
            float bc1 = sR[(r0+8)*36 + jj];
            #pragma unroll
            for (int nf = 0; nf < 8; nf++) {
                s[nf][0] = bc0; s[nf][1] = bc0;
                s[nf][2] = bc1; s[nf][3] = bc1;
            }
        } else {
            #pragma unroll
            for (int nf = 0; nf < 8; nf++) {
                int cc = s0 + nf*8 + 2*t;
                int d00 = cc - rowt0;     d00 = d00 < -16 ? -16 : (d00 > 16 ? 16 : d00);
                int d01 = cc + 1 - rowt0; d01 = d01 < -16 ? -16 : (d01 > 16 ? 16 : d01);
                int d10 = cc - rowt1;     d10 = d10 < -16 ? -16 : (d10 > 16 ? 16 : d10);
                int d11 = cc + 1 - rowt1; d11 = d11 < -16 ? -16 : (d11 > 16 ? 16 : d11);
                s[nf][0] = sR[r0*36 + d00 + 16];
                s[nf][1] = sR[r0*36 + d01 + 16];
                s[nf][2] = sR[(r0+8)*36 + d10 + 16];
                s[nf][3] = sR[(r0+8)*36 + d11 + 16];
            }
        }
        #pragma unroll
        for (int nfp = 0; nfp < 4; nfp++) {
            #pragma unroll
            for (int kc = 0; kc < 4; kc++) {
                unsigned b0a, b1a, b0b, b1b;
                ldsm4(b0a, b1a, b0b, b1b,
                      kx + laneK + (unsigned)((nfp*16*LDKH + kc*16)*2));
                mma16(s[2*nfp],   qa[kc], b0a, b1a);
                mma16(s[2*nfp+1], qa[kc], b0b, b1b);
            }
        }

        // row maxes (pure scan; bias already inside s)
        float mn0 = -INFINITY, mn1 = -INFINITY;
        #pragma unroll
        for (int nf = 0; nf < 8; nf++) {
            mn0 = fmaxf(mn0, fmaxf(s[nf][0], s[nf][1]));
            mn1 = fmaxf(mn1, fmaxf(s[nf][2], s[nf][3]));
        }
        mn0 = fmaxf(mn0, __shfl_xor_sync(0xffffffffu, mn0, 1));
        mn0 = fmaxf(mn0, __shfl_xor_sync(0xffffffffu, mn0, 2));
        mn1 = fmaxf(mn1, __shfl_xor_sync(0xffffffffu, mn1, 1));
        mn1 = fmaxf(mn1, __shfl_xor_sync(0xffffffffu, mn1, 2));
        float m0n = fmaxf(m0v, mn0);
        float m1n = fmaxf(m1v, mn1);
        const bool same = (m0n == m0v) && (m1n == m1v);
        const bool allsame = __all_sync(0xffffffffu, same);
        float a0 = 1.0f, a1 = 1.0f;
        if (!allsame) { a0 = ex2(m0v - m0n); a1 = ex2(m1v - m1n); }
        m0v = m0n; m1v = m1n;

        // P = exp2(s - m); pack straight into f16 A-operand layout
        float ls0 = 0.0f, ls1 = 0.0f;
        unsigned ph[8][2];
        #pragma unroll
        for (int nf = 0; nf < 8; nf++) {
            float p00 = ex2(s[nf][0] - m0n);
            float p01 = ex2(s[nf][1] - m0n);
            float p10 = ex2(s[nf][2] - m1n);
            float p11 = ex2(s[nf][3] - m1n);
            ls0 += p00 + p01;
            ls1 += p10 + p11;
            ph[nf][0] = h2u(__floats2half2_rn(p00, p01));  // row g
            ph[nf][1] = h2u(__floats2half2_rn(p10, p11));  // row g+8
        }
        ls0 += __shfl_xor_sync(0xffffffffu, ls0, 1);
        ls0 += __shfl_xor_sync(0xffffffffu, ls0, 2);
        ls1 += __shfl_xor_sync(0xffffffffu, ls1, 1);
        ls1 += __shfl_xor_sync(0xffffffffu, ls1, 2);
        l0 = l0*a0 + ls0;
        l1 = l1*a1 + ls1;
        if (!allsame) {
            #pragma unroll
            for (int dn = 0; dn < 8; dn++) {
                o[dn][0] *= a0; o[dn][1] *= a0;
                o[dn][2] *= a1; o[dn][3] *= a1;
            }
        }

        // O += P @ V   (16 x 64); V^T fragments via ldmatrix.x4.trans
        #pragma unroll
        for (int kc = 0; kc < 4; kc++) {
            unsigned a[4] = { ph[2*kc][0], ph[2*kc][1], ph[2*kc+1][0], ph[2*kc+1][1] };
            #pragma unroll
            for (int dnp = 0; dnp < 4; dnp++) {
                unsigned b0a, b1a, b0b, b1b;
                ldsm4t(b0a, b1a, b0b, b1b,
                       vx + laneV + (unsigned)((kc*16*LDKH + dnp*16)*2));
                mma16(o[2*dnp],   a, b0a, b1a);
                mma16(o[2*dnp+1], a, b0b, b1b);
            }
        }
    }

    // epilogue: normalize, write half [B,T,H*64]
    const int bb = bh / NHEAD, h = bh - bb*NHEAD;
    const float inv0 = 1.0f / l0;
    const float inv1 = 1.0f / l1;
    __half* o0 = g_attnh + ((size_t)(bb*SEQ + t0 + r0))*D_MODEL + h*64;
    __half* o1 = o0 + (size_t)8*D_MODEL;
    #pragma unroll
    for (int dn = 0; dn < 8; dn++) {
        *(__half2*)(o0 + dn*8 + 2*t) = __floats2half2_rn(o[dn][0]*inv0, o[dn][1]*inv0);
        *(__half2*)(o1 + dn*8 + 2*t) = __floats2half2_rn(o[dn][2]*inv1, o[dn][3]*inv1);
    }
}

// ---------------------------------------------------------------------------
extern "C" void kernel_launch(void* const* d_in, const int* in_sizes, int n_in,
                              void* d_out, int out_size)
{
    const float* x     = (const float*)d_in[0];
    const float* qkv_w = (const float*)d_in[1];
    const float* qkv_b = (const float*)d_in[2];
    const float* out_w = (const float*)d_in[3];
    const float* out_b = (const float*)d_in[4];
    const float* rel   = (const float*)d_in[5];
    float* out = (float*)d_out;

    (void)in_sizes; (void)n_in; (void)out_size;

    const int gemm_smem = 3*GST*2 + 128*4;                     // 111,104 B
    const int attn_smem = 3*KST*2 + 128*LDKH*2 + 128*36*4;     // 92,160 B
    cudaFuncSetAttribute(gemm_half, cudaFuncAttributeMaxDynamicSharedMemorySize, gemm_smem);
    cudaFuncSetAttribute(attn_flash, cudaFuncAttributeMaxDynamicSharedMemorySize, attn_smem);

    // 0) single fp32 -> fp16 conversion pre-pass (one launch)
    to_half_all<<<(N4_ALL + 255)/256, 256>>>(x, qkv_w, out_w, rel);
    // 1) QKV projection -> half q/k/v [B,H,T,64] (q pre-scaled by CSC)
    gemm_half<<<dim3(18, 32), 256, gemm_smem>>>(qkv_b, nullptr, 0);
    // 2) fused flash attention (rel projections via MMA, bias-seeded S)
    attn_flash<<<dim3(8, 48), 256, attn_smem>>>();
    // 3) output projection
    gemm_half<<<dim3(6, 32), 256, gemm_smem>>>(out_b, out, 1);
}

// round 16
// speedup vs baseline: 1.3401x; 1.0303x over previous
#include <cuda_runtime.h>
#include <cuda_fp16.h>
#include <math.h>

#define D_MODEL 768
#define NHEAD 12
#define HEAD_DIM 64
#define BATCH 4
#define SEQ 1024
#define MTOT (BATCH*SEQ)

// scratch (allocation-free requirement -> device globals)
__device__ __half g_xh[MTOT*D_MODEL];
__device__ __half g_wqkvh[3*D_MODEL*D_MODEL];
__device__ __half g_wouth[D_MODEL*D_MODEL];
__device__ __half g_relh[48*64];      // rel_pos_emb as half, rows 33..47 stay zero
__device__ __half g_qh[BATCH*NHEAD*SEQ*HEAD_DIM];
__device__ __half g_kh[BATCH*NHEAD*SEQ*HEAD_DIM];
__device__ __half g_vh[BATCH*NHEAD*SEQ*HEAD_DIM];
__device__ __half g_attnh[MTOT*D_MODEL];

#define CSC 0.18033688f   // 0.125 * log2(e)  (folded into q at QKV epilogue)

// ---------------------------------------------------------------------------
// helpers
// ---------------------------------------------------------------------------
__device__ __forceinline__ void cp16(void* s, const void* g) {
    unsigned sa = (unsigned)__cvta_generic_to_shared(s);
    asm volatile("cp.async.cg.shared.global [%0], [%1], 16;" :: "r"(sa), "l"(g));
}
#define CP_COMMIT() asm volatile("cp.async.commit_group;")
#define CP_WAIT1()  asm volatile("cp.async.wait_group 1;")

// bit-cast __half2 -> u32 (register reinterpret, no instruction)
__device__ __forceinline__ unsigned h2u(__half2 h) {
    __half2_raw hr = *(__half2_raw*)&h;
    unsigned u = (unsigned)hr.x | ((unsigned)hr.y << 16);
    return u;
}
// packed half2 exp2 (single MUFU op for two values)
__device__ __forceinline__ unsigned h2ex2(unsigned x) {
    unsigned r;
    asm("ex2.approx.f16x2 %0, %1;" : "=r"(r) : "r"(x));
    return r;
}
__device__ __forceinline__ float ex2(float x) {
    float r;
    asm("ex2.approx.ftz.f32 %0, %1;" : "=f"(r) : "f"(x));
    return r;
}

// warp-collective 8x8 b16 matrix loads
__device__ __forceinline__ void ldsm4(unsigned& r0, unsigned& r1, unsigned& r2,
                                      unsigned& r3, unsigned addr) {
    asm volatile("ldmatrix.sync.aligned.m8n8.x4.shared.b16 {%0,%1,%2,%3}, [%4];"
                 : "=r"(r0), "=r"(r1), "=r"(r2), "=r"(r3) : "r"(addr));
}
__device__ __forceinline__ void ldsm4t(unsigned& r0, unsigned& r1, unsigned& r2,
                                       unsigned& r3, unsigned addr) {
    asm volatile("ldmatrix.sync.aligned.m8n8.x4.trans.shared.b16 {%0,%1,%2,%3}, [%4];"
                 : "=r"(r0), "=r"(r1), "=r"(r2), "=r"(r3) : "r"(addr));
}
__device__ __forceinline__ void ldsm2t(unsigned& r0, unsigned& r1, unsigned addr) {
    asm volatile("ldmatrix.sync.aligned.m8n8.x2.trans.shared.b16 {%0,%1}, [%2];"
                 : "=r"(r0), "=r"(r1) : "r"(addr));
}

// mma.m16n8k16 f16 inputs, f32 accum (documented fragment layouts)
__device__ __forceinline__ void mma16(float* d, const unsigned* a, unsigned b0, unsigned b1) {
    asm volatile(
        "mma.sync.aligned.m16n8k16.row.col.f32.f16.f16.f32 "
        "{%0,%1,%2,%3}, {%4,%5,%6,%7}, {%8,%9}, {%0,%1,%2,%3};"
        : "+f"(d[0]), "+f"(d[1]), "+f"(d[2]), "+f"(d[3])
        : "r"(a[0]), "r"(a[1]), "r"(a[2]), "r"(a[3]), "r"(b0), "r"(b1));
}

// ---------------------------------------------------------------------------
// single fp32 -> fp16 conversion pre-pass for all inputs (one launch)
// ---------------------------------------------------------------------------
#define N4_X   (MTOT*D_MODEL/4)
#define N4_QW  (3*D_MODEL*D_MODEL/4)
#define N4_OW  (D_MODEL*D_MODEL/4)
#define N4_REL (33*64/4)
#define N4_ALL (N4_X + N4_QW + N4_OW + N4_REL)

__global__ void to_half_all(const float* __restrict__ x,
                            const float* __restrict__ qw,
                            const float* __restrict__ ow,
                            const float* __restrict__ rel)
{
    int i = blockIdx.x * blockDim.x + threadIdx.x;
    if (i >= N4_ALL) return;
    const float* src;
    __half2* dst;
    int off;
    if (i < N4_X)                        { src = x;   dst = (__half2*)g_xh;    off = i; }
    else if (i < N4_X + N4_QW)           { src = qw;  dst = (__half2*)g_wqkvh; off = i - N4_X; }
    else if (i < N4_X + N4_QW + N4_OW)   { src = ow;  dst = (__half2*)g_wouth; off = i - N4_X - N4_QW; }
    else                                 { src = rel; dst = (__half2*)g_relh;  off = i - N4_X - N4_QW - N4_OW; }
    float4 v = ((const float4*)src)[off];
    dst[off*2]   = __floats2half2_rn(v.x, v.y);
    dst[off*2+1] = __floats2half2_rn(v.z, v.w);
}

// ---------------------------------------------------------------------------
// fp16 GEMM (128x128 tile) for the QKV projection (mode 0 scatter epilogue)
// ---------------------------------------------------------------------------
#define LDH 72
#define GST (2*128*LDH)
__global__ __launch_bounds__(256, 2) void gemm_half(
    const float* __restrict__ bias)
{
    extern __shared__ __align__(16) char smraw[];
    __half* st = (__half*)smraw;                  // 3 stages x (A 128x72 | B 128x72)
    float*  sBias = (float*)(st + 3*GST);

    const __half* A = g_xh;
    const __half* W = g_wqkvh;

    const int n0 = blockIdx.x * 128;
    const int m0 = blockIdx.y * 128;
    const int tid = threadIdx.x;
    const int warp = tid >> 5;
    const int lane = tid & 31;
    const int g = lane >> 2;
    const int t = lane & 3;
    const int wm = warp & 3;
    const int wn = warp >> 2;

    const int lmat = lane >> 3, lrow = lane & 7;
    const unsigned laneA = ((unsigned)((lmat & 1)*8 + lrow))*(LDH*2) + (unsigned)(lmat >> 1)*16;
    const unsigned laneB = ((unsigned)((lmat >> 1)*8 + lrow))*(LDH*2) + (unsigned)(lmat & 1)*16;

    auto issue = [&](int kt, int s) {
        __half* as = st + s*GST;
        __half* bs = as + 128*LDH;
        #pragma unroll
        for (int u = 0; u < 4; u++) {
            int idx = tid + u*256;
            int r = idx >> 3, c8 = idx & 7;
            cp16(&as[r*LDH + c8*8], &A[(size_t)(m0 + r)*768 + kt + c8*8]);
        }
        #pragma unroll
        for (int u = 0; u < 4; u++) {
            int idx = tid + u*256;
            int r = idx >> 3, c8 = idx & 7;
            cp16(&bs[r*LDH + c8*8], &W[(size_t)(n0 + r)*768 + kt + c8*8]);
        }
        CP_COMMIT();
    };

    issue(0, 0);
    issue(64, 1);
    if (tid < 128) sBias[tid] = bias[n0 + tid];

    const unsigned stBase = (unsigned)__cvta_generic_to_shared(st);

    float c[2][8][4];
    #pragma unroll
    for (int mf = 0; mf < 2; mf++)
        #pragma unroll
        for (int nf = 0; nf < 8; nf++)
            #pragma unroll
            for (int e = 0; e < 4; e++) c[mf][nf][e] = 0.0f;

    for (int it = 0; it < 12; it++) {
        CP_WAIT1();
        __syncthreads();
        if (it + 2 < 12) issue((it + 2)*64, (it + 2) % 3);
        else CP_COMMIT();

        const unsigned as_s = stBase + (unsigned)((it % 3)*GST*2);
        const unsigned bs_s = as_s + 128*LDH*2;

        #pragma unroll
        for (int kc = 0; kc < 4; kc++) {
            unsigned a[2][4];
            #pragma unroll
            for (int mf = 0; mf < 2; mf++)
                ldsm4(a[mf][0], a[mf][1], a[mf][2], a[mf][3],
                      as_s + laneA + (unsigned)(((wm*32 + mf*16)*LDH + kc*16)*2));
            #pragma unroll
            for (int nfp = 0; nfp < 4; nfp++) {
                unsigned b0a, b1a, b0b, b1b;
                ldsm4(b0a, b1a, b0b, b1b,
                      bs_s + laneB + (unsigned)(((wn*64 + nfp*16)*LDH + kc*16)*2));
                mma16(c[0][2*nfp],   a[0], b0a, b1a);
                mma16(c[1][2*nfp],   a[1], b0a, b1a);
                mma16(c[0][2*nfp+1], a[0], b0b, b1b);
                mma16(c[1][2*nfp+1], a[1], b0b, b1b);
            }
        }
    }

    // scatter epilogue -> half q/k/v [B,H,T,64]; q pre-scaled by CSC
    #pragma unroll
    for (int mf = 0; mf < 2; mf++) {
        #pragma unroll
        for (int nf = 0; nf < 8; nf++) {
            int m = m0 + wm*32 + mf*16 + g;
            int n = n0 + wn*64 + nf*8 + 2*t;
            float bv0 = sBias[n - n0], bv1 = sBias[n - n0 + 1];
            float v00 = c[mf][nf][0] + bv0, v01 = c[mf][nf][1] + bv1;
            float v10 = c[mf][nf][2] + bv0, v11 = c[mf][nf][3] + bv1;
            int c3 = n / 768;
            int rem = n - c3*768;
            int h = rem >> 6, d = rem & 63;
            __half* dst = (c3 == 0) ? g_qh : (c3 == 1) ? g_kh : g_vh;
            if (c3 == 0) { v00 *= CSC; v01 *= CSC; v10 *= CSC; v11 *= CSC; }
            int bb = m >> 10, tt = m & 1023;
            size_t rowbase = ((size_t)(bb*NHEAD + h)*SEQ + tt)*64 + d;
            *(__half2*)&dst[rowbase]        = __floats2half2_rn(v00, v01);
            *(__half2*)&dst[rowbase + 8*64] = __floats2half2_rn(v10, v11);
        }
    }
}

// ---------------------------------------------------------------------------
// fp16 GEMM (64x128 tile) for the output projection: better wave quantization
// (grid 6x64 = 384 blocks vs 192). 8 warps = 2(m) x 4(n), warp tile 32x32.
// ---------------------------------------------------------------------------
#define GST64 ((64 + 128)*LDH)
__global__ __launch_bounds__(256, 2) void gemm_half64(
    const float* __restrict__ bias,
    float* __restrict__ Cout)
{
    extern __shared__ __align__(16) char smraw[];
    __half* st = (__half*)smraw;                 // 3 stages x (A 64x72 | B 128x72)
    float*  sBias = (float*)(st + 3*GST64);

    const __half* A = g_attnh;
    const __half* W = g_wouth;

    const int n0 = blockIdx.x * 128;
    const int m0 = blockIdx.y * 64;
    const int tid = threadIdx.x;
    const int warp = tid >> 5;
    const int lane = tid & 31;
    const int g = lane >> 2;
    const int t = lane & 3;
    const int wm = warp & 1;    // 2 m-slabs of 32
    const int wn = warp >> 1;   // 4 n-slabs of 32

    const int lmat = lane >> 3, lrow = lane & 7;
    const unsigned laneA = ((unsigned)((lmat & 1)*8 + lrow))*(LDH*2) + (unsigned)(lmat >> 1)*16;
    const unsigned laneB = ((unsigned)((lmat >> 1)*8 + lrow))*(LDH*2) + (unsigned)(lmat & 1)*16;

    auto issue = [&](int kt, int s) {
        __half* as = st + s*GST64;
        __half* bs = as + 64*LDH;
        #pragma unroll
        for (int u = 0; u < 2; u++) {
            int idx = tid + u*256;               // 512 x 16B for A (64 rows)
            int r = idx >> 3, c8 = idx & 7;
            cp16(&as[r*LDH + c8*8], &A[(size_t)(m0 + r)*768 + kt + c8*8]);
        }
        #pragma unroll
        for (int u = 0; u < 4; u++) {
            int idx = tid + u*256;               // 1024 x 16B for B (128 rows)
            int r = idx >> 3, c8 = idx & 7;
            cp16(&bs[r*LDH + c8*8], &W[(size_t)(n0 + r)*768 + kt + c8*8]);
        }
        CP_COMMIT();
    };

    issue(0, 0);
    issue(64, 1);
    if (tid < 128) sBias[tid] = bias[n0 + tid];

    const unsigned stBase = (unsigned)__cvta_generic_to_shared(st);

    float c[2][4][4];
    #pragma unroll
    for (int mf = 0; mf < 2; mf++)
        #pragma unroll
        for (int nf = 0; nf < 4; nf++)
            #pragma unroll
            for (int e = 0; e < 4; e++) c[mf][nf][e] = 0.0f;

    for (int it = 0; it < 12; it++) {
        CP_WAIT1();
        __syncthreads();
        if (it + 2 < 12) issue((it + 2)*64, (it + 2) % 3);
        else CP_COMMIT();

        const unsigned as_s = stBase + (unsigned)((it % 3)*GST64*2);
        const unsigned bs_s = as_s + 64*LDH*2;

        #pragma unroll
        for (int kc = 0; kc < 4; kc++) {
            unsigned a[2][4];
            #pragma unroll
            for (int mf = 0; mf < 2; mf++)
                ldsm4(a[mf][0], a[mf][1], a[mf][2], a[mf][3],
                      as_s + laneA + (unsigned)(((wm*32 + mf*16)*LDH + kc*16)*2));
            #pragma unroll
            for (int nfp = 0; nfp < 2; nfp++) {
                unsigned b0a, b1a, b0b, b1b;
                ldsm4(b0a, b1a, b0b, b1b,
                      bs_s + laneB + (unsigned)(((wn*32 + nfp*16)*LDH + kc*16)*2));
                mma16(c[0][2*nfp],   a[0], b0a, b1a);
                mma16(c[1][2*nfp],   a[1], b0a, b1a);
                mma16(c[0][2*nfp+1], a[0], b0b, b1b);
                mma16(c[1][2*nfp+1], a[1], b0b, b1b);
            }
        }
    }

    #pragma unroll
    for (int mf = 0; mf < 2; mf++) {
        #pragma unroll
        for (int nf = 0; nf < 4; nf++) {
            int m = m0 + wm*32 + mf*16 + g;
            int n = n0 + wn*32 + nf*8 + 2*t;
            float bv0 = sBias[n - n0], bv1 = sBias[n - n0 + 1];
            *(float2*)&Cout[(size_t)m*768 + n] =
                make_float2(c[mf][nf][0] + bv0, c[mf][nf][1] + bv1);
            *(float2*)&Cout[(size_t)(m+8)*768 + n] =
                make_float2(c[mf][nf][2] + bv0, c[mf][nf][3] + bv1);
        }
    }
}

// ---------------------------------------------------------------------------
// Flash attention, fp16 mma + ldmatrix; 3-stage KV ring, one barrier/iter.
// Row-sum folded into PV via a ones-column in the V pad (col 64); p computed
// with ex2.approx.f16x2. grid (8 q-tiles, 48 bh), 256 thr.
// ---------------------------------------------------------------------------
#define LDKH 72
#define KST (2*64*LDKH)

__global__ __launch_bounds__(256, 2) void attn_flash()
{
    extern __shared__ __align__(16) char saraw[];
    __half* stg = (__half*)saraw;               // 3 KV stages
    __half* sQ  = stg + 3*KST;                  // 128 x 72 halves
    float*  sR  = (float*)(sQ + 128*LDKH);      // 128 x 36 floats (pre-scaled bias)
    __half* sRel = stg + 2*KST;                 // overlays stage 2 K half: 48 x 72

    const int t0 = blockIdx.x * 128;
    const int bh = blockIdx.y;
    const int tid = threadIdx.x;
    const int w = tid >> 5;
    const int lane = tid & 31;
    const int g = lane >> 2;
    const int t = lane & 3;

    const __half* qb = g_qh + ((size_t)bh*SEQ + t0)*64;
    const __half* kb = g_kh + (size_t)bh*SEQ*64;
    const __half* vb = g_vh + (size_t)bh*SEQ*64;

    const int lmat = lane >> 3, lrow = lane & 7;
    const unsigned laneK = ((unsigned)((lmat >> 1)*8 + lrow))*(LDKH*2) + (unsigned)(lmat & 1)*16;
    const unsigned laneV = ((unsigned)((lmat & 1)*8 + lrow))*(LDKH*2) + (unsigned)(lmat >> 1)*16;
    const unsigned laneQ = ((unsigned)((lmat & 1)*8 + lrow))*(LDKH*2) + (unsigned)(lmat >> 1)*16;
    const unsigned laneVS = ((unsigned)((lmat & 1)*8 + lrow))*(LDKH*2) + 128;  // cols 64..71

    auto issueKV = [&](int s0, int stage) {
        __half* dK = stg + stage*KST;
        __half* dV = dK + 64*LDKH;
        #pragma unroll
        for (int u = 0; u < 2; u++) {
            int idx = tid + u*256;
            int r = idx >> 3, c8 = idx & 7;
            cp16(&dK[r*LDKH + c8*8], &kb[(size_t)(s0 + r)*64 + c8*8]);
            cp16(&dV[r*LDKH + c8*8], &vb[(size_t)(s0 + r)*64 + c8*8]);
        }
        CP_COMMIT();
    };

    issueKV(0, 0);                                 // G1: KV stage 0
    #pragma unroll
    for (int u = 0; u < 4; u++) {                  // G2: Q + rel
        int idx = tid + u*256;
        int r = idx >> 3, c8 = idx & 7;
        cp16(&sQ[r*LDKH + c8*8], &qb[(size_t)r*64 + c8*8]);
    }
    for (int idx = tid; idx < 48*8; idx += 256) {
        int r = idx >> 3, c8 = idx & 7;
        cp16(&sRel[r*LDKH + c8*8], &g_relh[r*64 + c8*8]);
    }
    CP_COMMIT();
    issueKV(64, 1);                                // G3: KV stage 1
    // V pad init (all 3 stages): col 64 = 1.0 (ones column for row sums),
    // cols 65..71 = 0. cp.async never writes cols >= 64, so pads persist.
    for (int idx = tid; idx < 3*64*4; idx += 256) {
        int sti = idx >> 8;
        int rem = idx & 255;
        int r = rem >> 2, c2 = rem & 3;
        __half2* p = (__half2*)(stg + sti*KST + 64*LDKH + r*LDKH + 64 + c2*2);
        *p = (c2 == 0) ? __halves2half2(__float2half(1.0f), __float2half(0.0f))
                       : __halves2half2(__float2half(0.0f), __float2half(0.0f));
    }
    CP_WAIT1();
    __syncthreads();

    // persistent Q A-fragments (q already CSC-scaled)
    const int r0 = w*16 + g;
    unsigned qa[4][4];
    {
        unsigned q_s = (unsigned)__cvta_generic_to_shared(sQ);
        #pragma unroll
        for (int kc = 0; kc < 4; kc++)
            ldsm4(qa[kc][0], qa[kc][1], qa[kc][2], qa[kc][3],
                  q_s + laneQ + (unsigned)((w*16*LDKH + kc*16)*2));
    }

    // R = Q @ rel^T via MMA (CSC pre-applied through q); store j<36
    {
        const unsigned rel_s = (unsigned)__cvta_generic_to_shared(sRel);
        float rr[6][4];
        #pragma unroll
        for (int nfp = 0; nfp < 3; nfp++) {
            rr[2*nfp][0] = rr[2*nfp][1] = rr[2*nfp][2] = rr[2*nfp][3] = 0.0f;
            rr[2*nfp+1][0] = rr[2*nfp+1][1] = rr[2*nfp+1][2] = rr[2*nfp+1][3] = 0.0f;
            #pragma unroll
            for (int kc = 0; kc < 4; kc++) {
                unsigned b0a, b1a, b0b, b1b;
                ldsm4(b0a, b1a, b0b, b1b,
                      rel_s + laneK + (unsigned)((nfp*16*LDKH + kc*16)*2));
                mma16(rr[2*nfp],   qa[kc], b0a, b1a);
                mma16(rr[2*nfp+1], qa[kc], b0b, b1b);
            }
        }
        #pragma unroll
        for (int nf = 0; nf < 5; nf++) {
            int col = nf*8 + 2*t;
            if (col < 36) {
                sR[r0*36 + col]         = rr[nf][0];
                sR[r0*36 + col + 1]     = rr[nf][1];
                sR[(r0+8)*36 + col]     = rr[nf][2];
                sR[(r0+8)*36 + col + 1] = rr[nf][3];
            }
        }
    }

    const unsigned stBase = (unsigned)__cvta_generic_to_shared(stg);

    // o[0..7] = output cols; o[8] = ones-column accumulator (row sums l)
    float o[9][4];
    #pragma unroll
    for (int i = 0; i < 9; i++)
        #pragma unroll
        for (int j = 0; j < 4; j++) o[i][j] = 0.0f;
    float m0v = -INFINITY, m1v = -INFINITY;

    const int rowt0 = t0 + r0, rowt1 = rowt0 + 8;

    for (int it = 0; it < 16; it++) {
        CP_WAIT1();
        __syncthreads();            // compute(it-1) done; prologue sR/pads settled
        if (it + 2 < 16) issueKV((it + 2)*64, (it + 2) % 3);
        else CP_COMMIT();

        const unsigned kx = stBase + (unsigned)((it % 3)*KST*2);
        const unsigned vx = kx + (unsigned)(64*LDKH*2);
        const int s0 = it * 64;

        // seed S accumulators with the rel bias (log2 domain), then MMA
        float s[8][4];
        const bool uni = (s0 >= t0 + 192) || (s0 + 128 <= t0);
        if (uni) {
            int jj = (s0 > t0) ? 32 : 0;
            float bc0 = sR[r0*36 + jj];
            float bc1 = sR[(r0+8)*36 + jj];
            #pragma unroll
            for (int nf = 0; nf < 8; nf++) {
                s[nf][0] = bc0; s[nf][1] = bc0;
                s[nf][2] = bc1; s[nf][3] = bc1;
            }
        } else {
            #pragma unroll
            for (int nf = 0; nf < 8; nf++) {
                int cc = s0 + nf*8 + 2*t;
                int d00 = cc - rowt0;     d00 = d00 < -16 ? -16 : (d00 > 16 ? 16 : d00);
                int d01 = cc + 1 - rowt0; d01 = d01 < -16 ? -16 : (d01 > 16 ? 16 : d01);
                int d10 = cc - rowt1;     d10 = d10 < -16 ? -16 : (d10 > 16 ? 16 : d10);
                int d11 = cc + 1 - rowt1; d11 = d11 < -16 ? -16 : (d11 > 16 ? 16 : d11);
                s[nf][0] = sR[r0*36 + d00 + 16];
                s[nf][1] = sR[r0*36 + d01 + 16];
                s[nf][2] = sR[(r0+8)*36 + d10 + 16];
                s[nf][3] = sR[(r0+8)*36 + d11 + 16];
            }
        }
        #pragma unroll
        for (int nfp = 0; nfp < 4; nfp++) {
            #pragma unroll
            for (int kc = 0; kc < 4; kc++) {
                unsigned b0a, b1a, b0b, b1b;
                ldsm4(b0a, b1a, b0b, b1b,
                      kx + laneK + (unsigned)((nfp*16*LDKH + kc*16)*2));
                mma16(s[2*nfp],   qa[kc], b0a, b1a);
                mma16(s[2*nfp+1], qa[kc], b0b, b1b);
            }
        }

        // row maxes
        float mn0 = -INFINITY, mn1 = -INFINITY;
        #pragma unroll
        for (int nf = 0; nf < 8; nf++) {
            mn0 = fmaxf(mn0, fmaxf(s[nf][0], s[nf][1]));
            mn1 = fmaxf(mn1, fmaxf(s[nf][2], s[nf][3]));
        }
        mn0 = fmaxf(mn0, __shfl_xor_sync(0xffffffffu, mn0, 1));
        mn0 = fmaxf(mn0, __shfl_xor_sync(0xffffffffu, mn0, 2));
        mn1 = fmaxf(mn1, __shfl_xor_sync(0xffffffffu, mn1, 1));
        mn1 = fmaxf(mn1, __shfl_xor_sync(0xffffffffu, mn1, 2));
        float m0n = fmaxf(m0v, mn0);
        float m1n = fmaxf(m1v, mn1);
        const bool allsame = __all_sync(0xffffffffu, (m0n == m0v) && (m1n == m1v));
        if (!allsame) {
            float a0 = ex2(m0v - m0n);
            float a1 = ex2(m1v - m1n);
            #pragma unroll
            for (int dn = 0; dn < 9; dn++) {
                o[dn][0] *= a0; o[dn][1] *= a0;
                o[dn][2] *= a1; o[dn][3] *= a1;
            }
        }
        m0v = m0n; m1v = m1n;

        // P = exp2(s - m) in packed half2 (row sums come from the ones column)
        unsigned ph[8][2];
        #pragma unroll
        for (int nf = 0; nf < 8; nf++) {
            ph[nf][0] = h2ex2(h2u(__floats2half2_rn(s[nf][0] - m0n, s[nf][1] - m0n)));
            ph[nf][1] = h2ex2(h2u(__floats2half2_rn(s[nf][2] - m1n, s[nf][3] - m1n)));
        }

        // O += P @ V_ext (cols 0..63 output, col 64 = row sum)
        #pragma unroll
        for (int kc = 0; kc < 4; kc++) {
            unsigned a[4] = { ph[2*kc][0], ph[2*kc][1], ph[2*kc+1][0], ph[2*kc+1][1] };
            #pragma unroll
            for (int dnp = 0; dnp < 4; dnp++) {
                unsigned b0a, b1a, b0b, b1b;
                ldsm4t(b0a, b1a, b0b, b1b,
                       vx + laneV + (unsigned)((kc*16*LDKH + dnp*16)*2));
                mma16(o[2*dnp],   a, b0a, b1a);
                mma16(o[2*dnp+1], a, b0b, b1b);
            }
            unsigned b0s, b1s;
            ldsm2t(b0s, b1s, vx + laneVS + (unsigned)((kc*16*LDKH)*2));
            mma16(o[8], a, b0s, b1s);
        }
    }

    // epilogue: l lives in o[8] (col 64, lane t=0 of each group)
    const float lsum0 = __shfl_sync(0xffffffffu, o[8][0], lane & ~3);
    const float lsum1 = __shfl_sync(0xffffffffu, o[8][2], lane & ~3);
    const int bb = bh / NHEAD, h = bh - bb*NHEAD;
    const float inv0 = 1.0f / lsum0;
    const float inv1 = 1.0f / lsum1;
    __half* o0 = g_attnh + ((size_t)(bb*SEQ + t0 + r0))*D_MODEL + h*64;
    __half* o1 = o0 + (size_t)8*D_MODEL;
    #pragma unroll
    for (int dn = 0; dn < 8; dn++) {
        *(__half2*)(o0 + dn*8 + 2*t) = __floats2half2_rn(o[dn][0]*inv0, o[dn][1]*inv0);
        *(__half2*)(o1 + dn*8 + 2*t) = __floats2half2_rn(o[dn][2]*inv1, o[dn][3]*inv1);
    }
}

// ---------------------------------------------------------------------------
extern "C" void kernel_launch(void* const* d_in, const int* in_sizes, int n_in,
                              void* d_out, int out_size)
{
    const float* x     = (const float*)d_in[0];
    const float* qkv_w = (const float*)d_in[1];
    const float* qkv_b = (const float*)d_in[2];
    const float* out_w = (const float*)d_in[3];
    const float* out_b = (const float*)d_in[4];
    const float* rel   = (const float*)d_in[5];
    float* out = (float*)d_out;

    (void)in_sizes; (void)n_in; (void)out_size;

    const int gemm_smem   = 3*GST*2 + 128*4;                   // 111,104 B
    const int gemm64_smem = 3*GST64*2 + 128*4;                 // 83,456 B
    const int attn_smem   = 3*KST*2 + 128*LDKH*2 + 128*36*4;   // 92,160 B
    cudaFuncSetAttribute(gemm_half,   cudaFuncAttributeMaxDynamicSharedMemorySize, gemm_smem);
    cudaFuncSetAttribute(gemm_half64, cudaFuncAttributeMaxDynamicSharedMemorySize, gemm64_smem);
    cudaFuncSetAttribute(attn_flash,  cudaFuncAttributeMaxDynamicSharedMemorySize, attn_smem);

    // 0) single fp32 -> fp16 conversion pre-pass
    to_half_all<<<(N4_ALL + 255)/256, 256>>>(x, qkv_w, out_w, rel);
    // 1) QKV projection -> half q/k/v [B,H,T,64] (q pre-scaled by CSC)
    gemm_half<<<dim3(18, 32), 256, gemm_smem>>>(qkv_b);
    // 2) fused flash attention (MMA rel bias, ones-column row sums, f16x2 exp)
    attn_flash<<<dim3(8, 48), 256, attn_smem>>>();
    // 3) output projection (64-row tiles -> 384 blocks)
    gemm_half64<<<dim3(6, 64), 256, gemm64_smem>>>(out_b, out);
}